// round 10
// baseline (speedup 1.0000x reference)
#include <cuda_runtime.h>
#include <cuda.h>
#include <cuda_bf16.h>
#include <cstdint>

#define S_   2048
#define D_   3072
#define NH_  24
#define DH_  128
#define M_   12288
#define FD_  15360   // D_ + M_
#define NHSD ((size_t)NH_ * S_ * DH_)
#define EPSV 1e-6f

// ---------------- scratch (device globals: no allocation allowed) ----------------
static __device__ __align__(16) float g_emb[3 * D_];
static __device__ __align__(16) __nv_bfloat16 g_nx_hi[(size_t)S_ * D_];
static __device__ __align__(16) __nv_bfloat16 g_nx_lo[(size_t)S_ * D_];
static __device__ __align__(16) float g_qkv[3 * NHSD];   // q,k,v sections
// split-bf16 q/k/v for tensor-core attention
static __device__ __align__(16) __nv_bfloat16 g_qsh[NHSD];
static __device__ __align__(16) __nv_bfloat16 g_qsl[NHSD];
static __device__ __align__(16) __nv_bfloat16 g_ksh[NHSD];
static __device__ __align__(16) __nv_bfloat16 g_ksl[NHSD];
static __device__ __align__(16) __nv_bfloat16 g_vsh[NHSD];
static __device__ __align__(16) __nv_bfloat16 g_vsl[NHSD];
static __device__ __align__(16) __nv_bfloat16 g_f_hi[(size_t)S_ * FD_];
static __device__ __align__(16) __nv_bfloat16 g_f_lo[(size_t)S_ * FD_];
// weights split into one big hi / lo buffer; q,k,v,mlp contiguous => fused N=21504 GEMM
#define WOFF_Q   0
#define WOFF_MLP 28311552
#define WOFF_OUT 66060288
#define WTOT     113246208
#define WSEG     9437184           // 3072*3072 elements (q,k,v and 4 mlp quarters)
static __device__ __align__(16) __nv_bfloat16 g_w_hi[(size_t)WTOT];
static __device__ __align__(16) __nv_bfloat16 g_w_lo[(size_t)WTOT];

// ---------------- PTX helpers (sm_80-level: valid on base sm_103 target) ----------------
__device__ __forceinline__ uint32_t smem_u32(const void* p) {
    uint32_t a;
    asm("{ .reg .u64 t; cvta.to.shared.u64 t, %1; cvt.u32.u64 %0, t; }" : "=r"(a) : "l"(p));
    return a;
}
#define CP_ASYNC16(saddr, gptr) \
    asm volatile("cp.async.cg.shared.global [%0], [%1], 16;" :: "r"(saddr), "l"(gptr) : "memory")
#define CP_COMMIT() asm volatile("cp.async.commit_group;" ::: "memory")
#define CP_WAIT1()  asm volatile("cp.async.wait_group 1;" ::: "memory")

#define LDSM4(r, addr) \
    asm volatile("ldmatrix.sync.aligned.m8n8.x4.shared.b16 {%0,%1,%2,%3}, [%4];" \
                 : "=r"((r)[0]), "=r"((r)[1]), "=r"((r)[2]), "=r"((r)[3]) : "r"(addr))
#define LDSM4T(r, addr) \
    asm volatile("ldmatrix.sync.aligned.m8n8.x4.trans.shared.b16 {%0,%1,%2,%3}, [%4];" \
                 : "=r"((r)[0]), "=r"((r)[1]), "=r"((r)[2]), "=r"((r)[3]) : "r"(addr))
#define MMA_BF16(d, a, b) \
    asm volatile("mma.sync.aligned.m16n8k16.row.col.f32.bf16.bf16.f32 " \
                 "{%0,%1,%2,%3}, {%4,%5,%6,%7}, {%8,%9}, {%0,%1,%2,%3};" \
                 : "+f"((d)[0]), "+f"((d)[1]), "+f"((d)[2]), "+f"((d)[3]) \
                 : "r"((a)[0]), "r"((a)[1]), "r"((a)[2]), "r"((a)[3]), \
                   "r"((b)[0]), "r"((b)[1]))

// ---------------- small helpers ----------------
__device__ __forceinline__ float gelu_tanh(float x) {
    float u = 0.7978845608028654f * (x + 0.044715f * x * x * x);
    float t = __expf(2.f * u);
    float th = 1.f - 2.f / (t + 1.f);
    return 0.5f * x * (1.f + th);
}
__device__ __forceinline__ void split2(float a, float b, uint32_t& h, uint32_t& l) {
    __nv_bfloat162 hb = __floats2bfloat162_rn(a, b);
    float2 hf = __bfloat1622float2(hb);
    __nv_bfloat162 lb = __floats2bfloat162_rn(a - hf.x, b - hf.y);
    h = *(uint32_t*)&hb;
    l = *(uint32_t*)&lb;
}

// ---------------- weight fp32 -> bf16 hi/lo splitters ----------------
__global__ void __launch_bounds__(256) convw_k(const float* __restrict__ src,
                                               __nv_bfloat16* __restrict__ hi,
                                               __nv_bfloat16* __restrict__ lo, int n4) {
    int base = blockIdx.x * 1024 + threadIdx.x;
#pragma unroll
    for (int u = 0; u < 4; u++) {
        int i = base + u * 256;
        if (i < n4) {
            float4 v = ((const float4*)src)[i];
            uint32_t h01, l01, h23, l23;
            split2(v.x, v.y, h01, l01);
            split2(v.z, v.w, h23, l23);
            *(uint2*)(hi + (size_t)i * 4) = make_uint2(h01, h23);
            *(uint2*)(lo + (size_t)i * 4) = make_uint2(l01, l23);
        }
    }
}
// q,k,v + 4 mlp quarters: 7 equal segments of WSEG elements in one launch
__global__ void __launch_bounds__(256) convall_k(const float* __restrict__ q,
                                                 const float* __restrict__ k,
                                                 const float* __restrict__ v,
                                                 const float* __restrict__ mlp,
                                                 __nv_bfloat16* __restrict__ hi,
                                                 __nv_bfloat16* __restrict__ lo) {
    const int seg = blockIdx.y;
    const float* src = (seg == 0) ? q : (seg == 1) ? k : (seg == 2) ? v
                     : mlp + (size_t)(seg - 3) * WSEG;
    size_t doff = (size_t)seg * WSEG;
    const int n4seg = WSEG / 4;
    int base = blockIdx.x * 1024 + threadIdx.x;
#pragma unroll
    for (int u = 0; u < 4; u++) {
        int i = base + u * 256;
        if (i < n4seg) {
            float4 w4 = ((const float4*)src)[i];
            uint32_t h01, l01, h23, l23;
            split2(w4.x, w4.y, h01, l01);
            split2(w4.z, w4.w, h23, l23);
            *(uint2*)(hi + doff + (size_t)i * 4) = make_uint2(h01, h23);
            *(uint2*)(lo + doff + (size_t)i * 4) = make_uint2(l01, l23);
        }
    }
}

// ---------------- emb = silu(temb) @ norm_w.T + norm_b ----------------
__global__ void __launch_bounds__(128) emb_k(const float* __restrict__ temb,
                                             const float* __restrict__ w,
                                             const float* __restrict__ b) {
    int row = blockIdx.x;
    const float4* wr = (const float4*)(w + (size_t)row * D_);
    const float4* tr = (const float4*)temb;
    float s = 0.f;
    for (int i = threadIdx.x; i < D_ / 4; i += 128) {
        float4 a = tr[i], c = wr[i];
        a.x *= 1.f / (1.f + __expf(-a.x));
        a.y *= 1.f / (1.f + __expf(-a.y));
        a.z *= 1.f / (1.f + __expf(-a.z));
        a.w *= 1.f / (1.f + __expf(-a.w));
        s += a.x * c.x + a.y * c.y + a.z * c.z + a.w * c.w;
    }
#pragma unroll
    for (int o = 16; o; o >>= 1) s += __shfl_down_sync(0xffffffffu, s, o);
    __shared__ float red[4];
    if ((threadIdx.x & 31) == 0) red[threadIdx.x >> 5] = s;
    __syncthreads();
    if (threadIdx.x == 0) g_emb[row] = red[0] + red[1] + red[2] + red[3] + b[row];
}

// ---------------- layernorm + scale/shift -> nx (bf16 hi/lo) ----------------
__global__ void __launch_bounds__(256) ln_k(const float* __restrict__ x) {
    int row = blockIdx.x, tid = threadIdx.x;
    const float4* xr = (const float4*)(x + (size_t)row * D_);
    float4 v[3];
    float s = 0.f, sq = 0.f;
#pragma unroll
    for (int i = 0; i < 3; i++) {
        v[i] = xr[tid + i * 256];
        s  += v[i].x + v[i].y + v[i].z + v[i].w;
        sq += v[i].x * v[i].x + v[i].y * v[i].y + v[i].z * v[i].z + v[i].w * v[i].w;
    }
    __shared__ float sh1[32], sh2[32];
#pragma unroll
    for (int o = 16; o; o >>= 1) {
        s  += __shfl_down_sync(0xffffffffu, s, o);
        sq += __shfl_down_sync(0xffffffffu, sq, o);
    }
    int w = tid >> 5;
    if ((tid & 31) == 0) { sh1[w] = s; sh2[w] = sq; }
    __syncthreads();
    if (tid < 8) { s = sh1[tid]; sq = sh2[tid]; } else { s = 0.f; sq = 0.f; }
    if (w == 0) {
#pragma unroll
        for (int o = 4; o; o >>= 1) {
            s  += __shfl_down_sync(0xffffffffu, s, o);
            sq += __shfl_down_sync(0xffffffffu, sq, o);
        }
        if (tid == 0) { sh1[0] = s; sh2[0] = sq; }
    }
    __syncthreads();
    float mu = sh1[0] * (1.f / D_);
    float var = sh2[0] * (1.f / D_) - mu * mu;
    float rstd = rsqrtf(var + EPSV);
    const float4* shp = (const float4*)g_emb;
    const float4* scp = (const float4*)(g_emb + D_);
#pragma unroll
    for (int i = 0; i < 3; i++) {
        int idx = tid + i * 256;
        float4 sc = scp[idx], sf = shp[idx], a = v[i], o;
        o.x = (a.x - mu) * rstd * (1.f + sc.x) + sf.x;
        o.y = (a.y - mu) * rstd * (1.f + sc.y) + sf.y;
        o.z = (a.z - mu) * rstd * (1.f + sc.z) + sf.z;
        o.w = (a.w - mu) * rstd * (1.f + sc.w) + sf.w;
        uint32_t h01, l01, h23, l23;
        split2(o.x, o.y, h01, l01);
        split2(o.z, o.w, h23, l23);
        *(uint2*)(g_nx_hi + (size_t)row * D_ + idx * 4) = make_uint2(h01, h23);
        *(uint2*)(g_nx_lo + (size_t)row * D_ + idx * 4) = make_uint2(l01, l23);
    }
}

// ---------------- split-bf16 mma.sync GEMM: C[M,N] = A[M,K] @ B[N,K]^T ----------------
// CTA tile 128x256, warp tile 64x64, BK=32 (two k16 sub-steps per sync), 3-stage
// cp.async pipeline, 1 CTA/SM. EPI 0: merged qkv (n0<9216, head scatter) + mlp
// (n0>=9216, gelu -> fused hi/lo). EPI 2: out proj (resid + gate*(+bias)).
#define RSTR  40                   // row stride halves (80B, conflict-free)
#define ATILE (128 * RSTR)         // 5120 halves
#define BTILE (256 * RSTR)         // 10240 halves
#define STGH  (2 * ATILE + 2 * BTILE)  // 30720 halves / stage
#define GSMEM (3 * STGH * 2)       // 184320 bytes

template <int EPI>
__global__ void __launch_bounds__(256, 1) mgemm_k(
    const __nv_bfloat16* __restrict__ Ah, const __nv_bfloat16* __restrict__ Al,
    const __nv_bfloat16* __restrict__ Bh, const __nv_bfloat16* __restrict__ Bl,
    int K, float* __restrict__ C, const float* __restrict__ bias,
    const float* __restrict__ gate, const float* __restrict__ resid,
    const float* __restrict__ mlpb,
    __nv_bfloat16* __restrict__ fhi, __nv_bfloat16* __restrict__ flo) {
    extern __shared__ __align__(16) __nv_bfloat16 sm[];
    const uint32_t sbase = smem_u32(sm);
    const int tid = threadIdx.x, lane = tid & 31, wid = tid >> 5;
    const int wm = wid & 1, wn = wid >> 1;           // 2 x 4 warp grid
    const int m0 = blockIdx.x * 128, n0 = blockIdx.y * 256;
    const int NKT = K >> 5;

    auto issue = [&](int stage, int kt) {
        const int k0 = kt * 32;
        const uint32_t sb = sbase + (uint32_t)stage * STGH * 2;
        // 3072 16B chunks; consecutive lanes -> consecutive rows (80B stride, bank-clean)
#pragma unroll
        for (int it = 0; it < 12; it++) {
            int t = tid + it * 256;
            if (t < 1024) {          // A: 8 groups of 128 rows
                int g = t >> 7, row = t & 127;
                int half = g >> 2, c = (g & 3) * 8;
                const __nv_bfloat16* gp = (half ? Al : Ah) + (size_t)(m0 + row) * K + k0 + c;
                CP_ASYNC16(sb + (uint32_t)(half * ATILE + row * RSTR + c) * 2, gp);
            } else {                 // B: 8 groups of 256 rows
                int tb = t - 1024;
                int g = tb >> 8, row = tb & 255;
                int half = g >> 2, c = (g & 3) * 8;
                const __nv_bfloat16* gp = (half ? Bl : Bh) + (size_t)(n0 + row) * K + k0 + c;
                CP_ASYNC16(sb + (uint32_t)(2 * ATILE + half * BTILE + row * RSTR + c) * 2, gp);
            }
        }
    };

    float acc[4][8][4];
#pragma unroll
    for (int i = 0; i < 4; i++)
#pragma unroll
        for (int j = 0; j < 8; j++)
#pragma unroll
            for (int u = 0; u < 4; u++) acc[i][j][u] = 0.f;

    issue(0, 0); CP_COMMIT();
    issue(1, 1); CP_COMMIT();

    const uint32_t aoff = (uint32_t)((wm * 64 + (lane & 15)) * RSTR + (lane >> 4) * 8) * 2;
    const uint32_t boff = (uint32_t)((wn * 64 + (lane >> 4) * 8 + (lane & 7)) * RSTR +
                                     ((lane >> 3) & 1) * 8) * 2;

    for (int kt = 0; kt < NKT; kt++) {
        CP_WAIT1();            // stage kt resident
        __syncthreads();       // all warps done reading stage kt-1
        if (kt + 2 < NKT) issue((kt + 2) % 3, kt + 2);   // overwrites stage kt-1: safe
        CP_COMMIT();

        const uint32_t sb = sbase + (uint32_t)(kt % 3) * (STGH * 2);
        const uint32_t sA = sb + aoff;
        const uint32_t sB = sb + 2 * (ATILE * 2) + boff;
#pragma unroll
        for (int s = 0; s < 2; s++) {
            uint32_t bfh[4][4], bfl[4][4];
#pragma unroll
            for (int jp = 0; jp < 4; jp++) {
                uint32_t bo = sB + s * 32 + jp * (16 * RSTR * 2);
                LDSM4(bfh[jp], bo);
                LDSM4(bfl[jp], bo + BTILE * 2);
            }
#pragma unroll
            for (int i = 0; i < 4; i++) {
                uint32_t ah[4], al[4];
                uint32_t ao = sA + s * 32 + i * (16 * RSTR * 2);
                LDSM4(ah, ao);
                LDSM4(al, ao + ATILE * 2);
#pragma unroll
                for (int j = 0; j < 8; j++) MMA_BF16(acc[i][j], ah, bfh[j >> 1] + (j & 1) * 2);
#pragma unroll
                for (int j = 0; j < 8; j++) MMA_BF16(acc[i][j], ah, bfl[j >> 1] + (j & 1) * 2);
#pragma unroll
                for (int j = 0; j < 8; j++) MMA_BF16(acc[i][j], al, bfh[j >> 1] + (j & 1) * 2);
            }
        }
    }

    // ---- epilogue ----
    int sec = 0, hq = 0;
    const float* bsel = bias;
    const bool is_qkv = (EPI == 0) && (n0 < 9216);
    if (is_qkv) {
        sec = blockIdx.y / 12;          // 12 CTAs of 256 cols per 3072-col section
        hq = blockIdx.y % 12;           // 2 heads per CTA
        bsel = (sec == 0) ? bias : (sec == 1) ? gate : resid;
    }
#pragma unroll
    for (int i = 0; i < 4; i++) {
        int r0 = m0 + wm * 64 + i * 16 + (lane >> 2);
#pragma unroll
        for (int j = 0; j < 8; j++) {
            int cloc = wn * 64 + j * 8 + (lane & 3) * 2;   // 0..255 within tile
            int cg = n0 + cloc;
            if (EPI == 0) {
                if (is_qkv) {
                    int head = hq * 2 + (cloc >> 7);
                    int ch = cloc & 127;
                    float b0 = bsel[head * 128 + ch], b1 = bsel[head * 128 + ch + 1];
                    float v00 = acc[i][j][0] + b0, v01 = acc[i][j][1] + b1;
                    float v10 = acc[i][j][2] + b0, v11 = acc[i][j][3] + b1;
                    size_t base = (((size_t)sec * NH_ + head) * S_ + r0) * DH_ + ch;
                    *(float2*)(C + base) = make_float2(v00, v01);
                    *(float2*)(C + base + 8 * DH_) = make_float2(v10, v11);
                } else {
                    int col = cg - 9216;
                    float b0 = mlpb[col], b1 = mlpb[col + 1];
                    float v00 = gelu_tanh(acc[i][j][0] + b0), v01 = gelu_tanh(acc[i][j][1] + b1);
                    float v10 = gelu_tanh(acc[i][j][2] + b0), v11 = gelu_tanh(acc[i][j][3] + b1);
                    uint32_t h0, l0, h1, l1;
                    split2(v00, v01, h0, l0);
                    split2(v10, v11, h1, l1);
                    size_t base = (size_t)r0 * FD_ + D_ + col;
                    *(uint32_t*)(fhi + base) = h0;
                    *(uint32_t*)(flo + base) = l0;
                    *(uint32_t*)(fhi + base + (size_t)8 * FD_) = h1;
                    *(uint32_t*)(flo + base + (size_t)8 * FD_) = l1;
                }
            } else {
                float b0 = bias[cg], b1 = bias[cg + 1];
                float g0 = gate[cg], g1 = gate[cg + 1];
                size_t base = (size_t)r0 * D_ + cg;
                float2 rv0 = *(const float2*)(resid + base);
                float2 rv1 = *(const float2*)(resid + base + 8 * D_);
                *(float2*)(C + base) = make_float2(rv0.x + g0 * (acc[i][j][0] + b0),
                                                   rv0.y + g1 * (acc[i][j][1] + b1));
                *(float2*)(C + base + 8 * D_) = make_float2(rv1.x + g0 * (acc[i][j][2] + b0),
                                                            rv1.y + g1 * (acc[i][j][3] + b1));
            }
        }
    }
}

// ---------------- per-head RMSNorm + RoPE + bf16 hi/lo split (q,k,v) ----------------
__global__ void __launch_bounds__(128) rmsrope_k(const float* __restrict__ cosb,
                                                 const float* __restrict__ sinb,
                                                 const float* __restrict__ qrw,
                                                 const float* __restrict__ krw) {
    int s = blockIdx.x, h = blockIdx.y, j = threadIdx.x;
    size_t idx = ((size_t)h * S_ + s) * DH_ + j;
    float qv = g_qkv[idx], kv = g_qkv[NHSD + idx], vv = g_qkv[2 * NHSD + idx];
    float q2 = qv * qv, k2 = kv * kv;
#pragma unroll
    for (int o = 16; o; o >>= 1) {
        q2 += __shfl_xor_sync(0xffffffffu, q2, o);
        k2 += __shfl_xor_sync(0xffffffffu, k2, o);
    }
    __shared__ float sq[4], sk[4];
    int w = j >> 5;
    if ((j & 31) == 0) { sq[w] = q2; sk[w] = k2; }
    __syncthreads();
    float qsum = sq[0] + sq[1] + sq[2] + sq[3];
    float ksum = sk[0] + sk[1] + sk[2] + sk[3];
    float qr = rsqrtf(qsum * (1.f / DH_) + EPSV);
    float kr = rsqrtf(ksum * (1.f / DH_) + EPSV);
    qv *= qr * qrw[j];
    kv *= kr * krw[j];
    float qp = __shfl_xor_sync(0xffffffffu, qv, 1);
    float kp = __shfl_xor_sync(0xffffffffu, kv, 1);
    float qrot = (j & 1) ? qp : -qp;
    float krot = (j & 1) ? kp : -kp;
    float c = cosb[s * DH_ + j], sn = sinb[s * DH_ + j];
    float qf = qv * c + qrot * sn;
    float kf = kv * c + krot * sn;
    __nv_bfloat16 qh = __float2bfloat16(qf);
    __nv_bfloat16 kh = __float2bfloat16(kf);
    __nv_bfloat16 vh = __float2bfloat16(vv);
    g_qsh[idx] = qh; g_qsl[idx] = __float2bfloat16(qf - __bfloat162float(qh));
    g_ksh[idx] = kh; g_ksl[idx] = __float2bfloat16(kf - __bfloat162float(kh));
    g_vsh[idx] = vh; g_vsl[idx] = __float2bfloat16(vv - __bfloat162float(vh));
}

// ---------------- tensor-core flash attention ----------------
// 8 warps, q tile 128 (16 rows/warp), kv tile 64, split-bf16 3-pass QK^T and P.V
#define ASTR   136
#define QHALF  (128 * ASTR)
#define KVHALF (64 * ASTR)
#define STGHALF (4 * KVHALF)
#define ATT2_SMEM ((2 * QHALF + 2 * STGHALF) * 2)   // 208896 bytes

__global__ void __launch_bounds__(256, 1) attn2_k(__nv_bfloat16* __restrict__ fh,
                                                  __nv_bfloat16* __restrict__ fl) {
    extern __shared__ __align__(16) char smraw[];
    const uint32_t sb = smem_u32(smraw);
    const int tid = threadIdx.x, lane = tid & 31, wid = tid >> 5;
    const int h = blockIdx.y, qt = blockIdx.x;
    const __nv_bfloat16* Qgh = g_qsh + ((size_t)h * S_ + (size_t)qt * 128) * DH_;
    const __nv_bfloat16* Qgl = g_qsl + ((size_t)h * S_ + (size_t)qt * 128) * DH_;
    const __nv_bfloat16* Kgh = g_ksh + (size_t)h * S_ * DH_;
    const __nv_bfloat16* Kgl = g_ksl + (size_t)h * S_ * DH_;
    const __nv_bfloat16* Vgh = g_vsh + (size_t)h * S_ * DH_;
    const __nv_bfloat16* Vgl = g_vsl + (size_t)h * S_ * DH_;

    const uint32_t uQh = sb, uQl = sb + QHALF * 2;
    const uint32_t uStage = sb + 2 * QHALF * 2;

    auto issueKV = [&](int st, int kt) {
        uint32_t base = uStage + (uint32_t)st * STGHALF * 2;
#pragma unroll
        for (int it = 0; it < 16; it++) {
            int cidx = tid + it * 256;
            int mat = cidx >> 10, rem = cidx & 1023;
            int row = rem >> 4, c8 = rem & 15;
            const __nv_bfloat16* src;
            if (mat == 0) src = Kgh; else if (mat == 1) src = Kgl;
            else if (mat == 2) src = Vgh; else src = Vgl;
            CP_ASYNC16(base + (uint32_t)(mat * KVHALF + row * ASTR + c8 * 8) * 2,
                       src + ((size_t)(kt * 64 + row)) * DH_ + c8 * 8);
        }
    };
#pragma unroll
    for (int it = 0; it < 8; it++) {
        int cidx = tid + it * 256;
        int row = cidx >> 4, c8 = cidx & 15;
        CP_ASYNC16(uQh + (uint32_t)(row * ASTR + c8 * 8) * 2, Qgh + (size_t)row * DH_ + c8 * 8);
        CP_ASYNC16(uQl + (uint32_t)(row * ASTR + c8 * 8) * 2, Qgl + (size_t)row * DH_ + c8 * 8);
    }
    issueKV(0, 0); CP_COMMIT();
    issueKV(1, 1); CP_COMMIT();

    float o[16][4];
#pragma unroll
    for (int n = 0; n < 16; n++)
#pragma unroll
        for (int u = 0; u < 4; u++) o[n][u] = 0.f;
    float m0 = -3.0e38f, m1 = -3.0e38f, l0 = 0.f, l1 = 0.f;
    const int r0 = wid * 16;
    const float scale = 0.08838834764831845f;

    for (int kt = 0; kt < S_ / 64; kt++) {
        CP_WAIT1();
        __syncthreads();
        const uint32_t base = uStage + (uint32_t)(kt & 1) * STGHALF * 2;

        float sc[8][4];
#pragma unroll
        for (int n = 0; n < 8; n++)
#pragma unroll
            for (int u = 0; u < 4; u++) sc[n][u] = 0.f;
#pragma unroll
        for (int kc = 0; kc < 8; kc++) {
            uint32_t qh4[4], ql4[4];
            uint32_t qoff = (uint32_t)((r0 + (lane & 15)) * ASTR + kc * 16 + (lane >> 4) * 8) * 2;
            LDSM4(qh4, uQh + qoff);
            LDSM4(ql4, uQl + qoff);
            uint32_t kh4[4][4], kl4[4][4];
#pragma unroll
            for (int jp = 0; jp < 4; jp++) {
                uint32_t koff = base + (uint32_t)(((2 * jp + (lane >> 4)) * 8 + (lane & 7)) * ASTR +
                                                  kc * 16 + ((lane >> 3) & 1) * 8) * 2;
                LDSM4(kh4[jp], koff);
                LDSM4(kl4[jp], koff + KVHALF * 2);
            }
#pragma unroll
            for (int jp = 0; jp < 4; jp++) {
                MMA_BF16(sc[2 * jp],     qh4, kh4[jp]);
                MMA_BF16(sc[2 * jp + 1], qh4, kh4[jp] + 2);
            }
#pragma unroll
            for (int jp = 0; jp < 4; jp++) {
                MMA_BF16(sc[2 * jp],     qh4, kl4[jp]);
                MMA_BF16(sc[2 * jp + 1], qh4, kl4[jp] + 2);
            }
#pragma unroll
            for (int jp = 0; jp < 4; jp++) {
                MMA_BF16(sc[2 * jp],     ql4, kh4[jp]);
                MMA_BF16(sc[2 * jp + 1], ql4, kh4[jp] + 2);
            }
        }
        float mx0 = -3.0e38f, mx1 = -3.0e38f;
#pragma unroll
        for (int n = 0; n < 8; n++) {
            sc[n][0] *= scale; sc[n][1] *= scale; sc[n][2] *= scale; sc[n][3] *= scale;
            mx0 = fmaxf(mx0, fmaxf(sc[n][0], sc[n][1]));
            mx1 = fmaxf(mx1, fmaxf(sc[n][2], sc[n][3]));
        }
        mx0 = fmaxf(mx0, __shfl_xor_sync(0xffffffffu, mx0, 1));
        mx0 = fmaxf(mx0, __shfl_xor_sync(0xffffffffu, mx0, 2));
        mx1 = fmaxf(mx1, __shfl_xor_sync(0xffffffffu, mx1, 1));
        mx1 = fmaxf(mx1, __shfl_xor_sync(0xffffffffu, mx1, 2));
        float m0n = fmaxf(m0, mx0), m1n = fmaxf(m1, mx1);
        float c0 = __expf(m0 - m0n), c1 = __expf(m1 - m1n);
        m0 = m0n; m1 = m1n;
        uint32_t pah[4][4], pal[4][4];
        float s0 = 0.f, s1 = 0.f;
#pragma unroll
        for (int t = 0; t < 4; t++) {
            float p00 = __expf(sc[2 * t][0] - m0n),     p01 = __expf(sc[2 * t][1] - m0n);
            float p02 = __expf(sc[2 * t][2] - m1n),     p03 = __expf(sc[2 * t][3] - m1n);
            float p10 = __expf(sc[2 * t + 1][0] - m0n), p11 = __expf(sc[2 * t + 1][1] - m0n);
            float p12 = __expf(sc[2 * t + 1][2] - m1n), p13 = __expf(sc[2 * t + 1][3] - m1n);
            s0 += p00 + p01 + p10 + p11;
            s1 += p02 + p03 + p12 + p13;
            split2(p00, p01, pah[t][0], pal[t][0]);
            split2(p02, p03, pah[t][1], pal[t][1]);
            split2(p10, p11, pah[t][2], pal[t][2]);
            split2(p12, p13, pah[t][3], pal[t][3]);
        }
        s0 += __shfl_xor_sync(0xffffffffu, s0, 1);
        s0 += __shfl_xor_sync(0xffffffffu, s0, 2);
        s1 += __shfl_xor_sync(0xffffffffu, s1, 1);
        s1 += __shfl_xor_sync(0xffffffffu, s1, 2);
        l0 = l0 * c0 + s0;
        l1 = l1 * c1 + s1;
#pragma unroll
        for (int n = 0; n < 16; n++) {
            o[n][0] *= c0; o[n][1] *= c0; o[n][2] *= c1; o[n][3] *= c1;
        }
#pragma unroll
        for (int t = 0; t < 4; t++) {
#pragma unroll
            for (int dp = 0; dp < 8; dp += 2) {
                uint32_t vh4[2][4], vl4[2][4];
#pragma unroll
                for (int u = 0; u < 2; u++) {
                    uint32_t voff = base + (uint32_t)(2 * KVHALF +
                                    (t * 16 + (lane & 7) + ((lane & 8) ? 8 : 0)) * ASTR +
                                    (dp + u) * 16 + ((lane & 16) ? 8 : 0)) * 2;
                    LDSM4T(vh4[u], voff);
                    LDSM4T(vl4[u], voff + KVHALF * 2);
                }
#pragma unroll
                for (int u = 0; u < 2; u++) {
                    MMA_BF16(o[2 * (dp + u)],     pah[t], vh4[u]);
                    MMA_BF16(o[2 * (dp + u) + 1], pah[t], vh4[u] + 2);
                }
#pragma unroll
                for (int u = 0; u < 2; u++) {
                    MMA_BF16(o[2 * (dp + u)],     pah[t], vl4[u]);
                    MMA_BF16(o[2 * (dp + u) + 1], pah[t], vl4[u] + 2);
                }
#pragma unroll
                for (int u = 0; u < 2; u++) {
                    MMA_BF16(o[2 * (dp + u)],     pal[t], vh4[u]);
                    MMA_BF16(o[2 * (dp + u) + 1], pal[t], vh4[u] + 2);
                }
            }
        }
        __syncthreads();
        if (kt + 2 < S_ / 64) issueKV(kt & 1, kt + 2);
        CP_COMMIT();
    }
    float inv0 = 1.f / l0, inv1 = 1.f / l1;
    int ra = qt * 128 + r0 + (lane >> 2);
    int rb = ra + 8;
    int cb = h * DH_ + (lane & 3) * 2;
#pragma unroll
    for (int dn = 0; dn < 16; dn++) {
        uint32_t hh, ll;
        split2(o[dn][0] * inv0, o[dn][1] * inv0, hh, ll);
        *(uint32_t*)(fh + (size_t)ra * FD_ + cb + dn * 8) = hh;
        *(uint32_t*)(fl + (size_t)ra * FD_ + cb + dn * 8) = ll;
        split2(o[dn][2] * inv1, o[dn][3] * inv1, hh, ll);
        *(uint32_t*)(fh + (size_t)rb * FD_ + cb + dn * 8) = hh;
        *(uint32_t*)(fl + (size_t)rb * FD_ + cb + dn * 8) = ll;
    }
}

// ---------------- launch ----------------
extern "C" void kernel_launch(void* const* d_in, const int* in_sizes, int n_in,
                              void* d_out, int out_size) {
    (void)in_sizes; (void)n_in; (void)out_size;
    const float* hidden = (const float*)d_in[0];
    const float* temb   = (const float*)d_in[1];
    const float* cosb   = (const float*)d_in[2];
    const float* sinb   = (const float*)d_in[3];
    const float* norm_w = (const float*)d_in[4];
    const float* norm_b = (const float*)d_in[5];
    const float* qw = (const float*)d_in[6];
    const float* qb = (const float*)d_in[7];
    const float* kw = (const float*)d_in[8];
    const float* kb = (const float*)d_in[9];
    const float* vw = (const float*)d_in[10];
    const float* vb = (const float*)d_in[11];
    const float* qrw = (const float*)d_in[12];
    const float* krw = (const float*)d_in[13];
    const float* mlp_w = (const float*)d_in[14];
    const float* mlp_b = (const float*)d_in[15];
    const float* out_w = (const float*)d_in[16];
    const float* out_b = (const float*)d_in[17];
    float* out = (float*)d_out;

    void *p_qkv, *p_fh, *p_fl, *p_emb, *p_wh, *p_wl, *p_nxh, *p_nxl;
    cudaGetSymbolAddress(&p_nxh, g_nx_hi);
    cudaGetSymbolAddress(&p_nxl, g_nx_lo);
    cudaGetSymbolAddress(&p_qkv, g_qkv);
    cudaGetSymbolAddress(&p_fh, g_f_hi);
    cudaGetSymbolAddress(&p_fl, g_f_lo);
    cudaGetSymbolAddress(&p_emb, g_emb);
    cudaGetSymbolAddress(&p_wh, g_w_hi);
    cudaGetSymbolAddress(&p_wl, g_w_lo);
    __nv_bfloat16* wh = (__nv_bfloat16*)p_wh;
    __nv_bfloat16* wl = (__nv_bfloat16*)p_wl;
    const __nv_bfloat16* nxh = (const __nv_bfloat16*)p_nxh;
    const __nv_bfloat16* nxl = (const __nv_bfloat16*)p_nxl;
    const __nv_bfloat16* fh = (const __nv_bfloat16*)p_fh;
    const __nv_bfloat16* fl = (const __nv_bfloat16*)p_fl;

    cudaFuncSetAttribute(mgemm_k<0>, cudaFuncAttributeMaxDynamicSharedMemorySize, GSMEM);
    cudaFuncSetAttribute(mgemm_k<2>, cudaFuncAttributeMaxDynamicSharedMemorySize, GSMEM);
    cudaFuncSetAttribute(attn2_k, cudaFuncAttributeMaxDynamicSharedMemorySize, ATT2_SMEM);

    dim3 gfused(S_ / 128, (9216 + M_) / 256);   // 16 x 84, fused q/k/v + mlp
    dim3 go(S_ / 128, D_ / 256);                // 16 x 12

    convall_k<<<dim3((WSEG / 4 + 1023) / 1024, 7), 256>>>(qw, kw, vw, mlp_w, wh, wl);      // 0
    emb_k<<<3 * D_, 128>>>(temb, norm_w, norm_b);                                          // 1
    ln_k<<<S_, 256>>>(hidden);                                                             // 2
    mgemm_k<0><<<gfused, 256, GSMEM>>>(nxh, nxl, wh, wl, D_,                               // 3
                                       (float*)p_qkv, qb, kb, vb, mlp_b,
                                       (__nv_bfloat16*)p_fh, (__nv_bfloat16*)p_fl);
    rmsrope_k<<<dim3(S_, NH_), 128>>>(cosb, sinb, qrw, krw);                               // 4
    attn2_k<<<dim3(S_ / 128, NH_), 256, ATT2_SMEM>>>((__nv_bfloat16*)p_fh,                 // 5
                                                     (__nv_bfloat16*)p_fl);
    convw_k<<<(47185920 / 4 + 1023) / 1024, 256>>>(out_w, wh + WOFF_OUT, wl + WOFF_OUT,    // 6
                                                   47185920 / 4);
    mgemm_k<2><<<go, 256, GSMEM>>>(fh, fl, wh + WOFF_OUT, wl + WOFF_OUT, FD_, out, out_b,  // 7
                                   (const float*)p_emb + 2 * D_, hidden, nullptr,
                                   nullptr, nullptr);
}

// round 11
// speedup vs baseline: 1.2830x; 1.2830x over previous
#include <cuda_runtime.h>
#include <cuda.h>
#include <cuda_bf16.h>
#include <cstdint>

#define S_   2048
#define D_   3072
#define NH_  24
#define DH_  128
#define M_   12288
#define FD_  15360   // D_ + M_
#define NHSD ((size_t)NH_ * S_ * DH_)
#define EPSV 1e-6f

// ---------------- scratch (device globals: no allocation allowed) ----------------
static __device__ __align__(16) float g_emb[3 * D_];
static __device__ __align__(16) __nv_bfloat16 g_nx_hi[(size_t)S_ * D_];
static __device__ __align__(16) __nv_bfloat16 g_nx_lo[(size_t)S_ * D_];
static __device__ __align__(16) float g_qkv[3 * NHSD];   // q,k,v sections
// split-bf16 q/k/v for tensor-core attention
static __device__ __align__(16) __nv_bfloat16 g_qsh[NHSD];
static __device__ __align__(16) __nv_bfloat16 g_qsl[NHSD];
static __device__ __align__(16) __nv_bfloat16 g_ksh[NHSD];
static __device__ __align__(16) __nv_bfloat16 g_ksl[NHSD];
static __device__ __align__(16) __nv_bfloat16 g_vsh[NHSD];
static __device__ __align__(16) __nv_bfloat16 g_vsl[NHSD];
static __device__ __align__(16) __nv_bfloat16 g_f_hi[(size_t)S_ * FD_];
static __device__ __align__(16) __nv_bfloat16 g_f_lo[(size_t)S_ * FD_];
// split-K partials for out projection (3 x S x D fp32)
static __device__ __align__(16) float g_part[(size_t)3 * S_ * D_];
// weights split into one big hi / lo buffer; q,k,v,mlp contiguous => fused N=21504 GEMM
#define WOFF_OUT 66060288
#define WTOT     113246208
#define WSEG     9437184           // 3072*3072 elements (q,k,v and 4 mlp quarters)
static __device__ __align__(16) __nv_bfloat16 g_w_hi[(size_t)WTOT];
static __device__ __align__(16) __nv_bfloat16 g_w_lo[(size_t)WTOT];

// ---------------- PTX helpers (sm_80-level: valid on base sm_103 target) ----------------
__device__ __forceinline__ uint32_t smem_u32(const void* p) {
    uint32_t a;
    asm("{ .reg .u64 t; cvta.to.shared.u64 t, %1; cvt.u32.u64 %0, t; }" : "=r"(a) : "l"(p));
    return a;
}
#define CP_ASYNC16(saddr, gptr) \
    asm volatile("cp.async.cg.shared.global [%0], [%1], 16;" :: "r"(saddr), "l"(gptr) : "memory")
#define CP_COMMIT() asm volatile("cp.async.commit_group;" ::: "memory")
#define CP_WAIT1()  asm volatile("cp.async.wait_group 1;" ::: "memory")

#define LDSM4(r, addr) \
    asm volatile("ldmatrix.sync.aligned.m8n8.x4.shared.b16 {%0,%1,%2,%3}, [%4];" \
                 : "=r"((r)[0]), "=r"((r)[1]), "=r"((r)[2]), "=r"((r)[3]) : "r"(addr))
#define LDSM4T(r, addr) \
    asm volatile("ldmatrix.sync.aligned.m8n8.x4.trans.shared.b16 {%0,%1,%2,%3}, [%4];" \
                 : "=r"((r)[0]), "=r"((r)[1]), "=r"((r)[2]), "=r"((r)[3]) : "r"(addr))
#define MMA_BF16(d, a, b) \
    asm volatile("mma.sync.aligned.m16n8k16.row.col.f32.bf16.bf16.f32 " \
                 "{%0,%1,%2,%3}, {%4,%5,%6,%7}, {%8,%9}, {%0,%1,%2,%3};" \
                 : "+f"((d)[0]), "+f"((d)[1]), "+f"((d)[2]), "+f"((d)[3]) \
                 : "r"((a)[0]), "r"((a)[1]), "r"((a)[2]), "r"((a)[3]), \
                   "r"((b)[0]), "r"((b)[1]))

// ---------------- small helpers ----------------
__device__ __forceinline__ float gelu_tanh(float x) {
    float u = 0.7978845608028654f * (x + 0.044715f * x * x * x);
    float t = __expf(2.f * u);
    float th = 1.f - 2.f / (t + 1.f);
    return 0.5f * x * (1.f + th);
}
__device__ __forceinline__ void split2(float a, float b, uint32_t& h, uint32_t& l) {
    __nv_bfloat162 hb = __floats2bfloat162_rn(a, b);
    float2 hf = __bfloat1622float2(hb);
    __nv_bfloat162 lb = __floats2bfloat162_rn(a - hf.x, b - hf.y);
    h = *(uint32_t*)&hb;
    l = *(uint32_t*)&lb;
}

// ---------------- weight fp32 -> bf16 hi/lo splitters ----------------
__global__ void __launch_bounds__(256) convw_k(const float* __restrict__ src,
                                               __nv_bfloat16* __restrict__ hi,
                                               __nv_bfloat16* __restrict__ lo, int n4) {
    int base = blockIdx.x * 1024 + threadIdx.x;
#pragma unroll
    for (int u = 0; u < 4; u++) {
        int i = base + u * 256;
        if (i < n4) {
            float4 v = ((const float4*)src)[i];
            uint32_t h01, l01, h23, l23;
            split2(v.x, v.y, h01, l01);
            split2(v.z, v.w, h23, l23);
            *(uint2*)(hi + (size_t)i * 4) = make_uint2(h01, h23);
            *(uint2*)(lo + (size_t)i * 4) = make_uint2(l01, l23);
        }
    }
}
// q,k,v + 4 mlp quarters: 7 equal segments of WSEG elements in one launch
__global__ void __launch_bounds__(256) convall_k(const float* __restrict__ q,
                                                 const float* __restrict__ k,
                                                 const float* __restrict__ v,
                                                 const float* __restrict__ mlp,
                                                 __nv_bfloat16* __restrict__ hi,
                                                 __nv_bfloat16* __restrict__ lo) {
    const int seg = blockIdx.y;
    const float* src = (seg == 0) ? q : (seg == 1) ? k : (seg == 2) ? v
                     : mlp + (size_t)(seg - 3) * WSEG;
    size_t doff = (size_t)seg * WSEG;
    const int n4seg = WSEG / 4;
    int base = blockIdx.x * 1024 + threadIdx.x;
#pragma unroll
    for (int u = 0; u < 4; u++) {
        int i = base + u * 256;
        if (i < n4seg) {
            float4 w4 = ((const float4*)src)[i];
            uint32_t h01, l01, h23, l23;
            split2(w4.x, w4.y, h01, l01);
            split2(w4.z, w4.w, h23, l23);
            *(uint2*)(hi + doff + (size_t)i * 4) = make_uint2(h01, h23);
            *(uint2*)(lo + doff + (size_t)i * 4) = make_uint2(l01, l23);
        }
    }
}

// ---------------- emb = silu(temb) @ norm_w.T + norm_b ----------------
__global__ void __launch_bounds__(128) emb_k(const float* __restrict__ temb,
                                             const float* __restrict__ w,
                                             const float* __restrict__ b) {
    int row = blockIdx.x;
    const float4* wr = (const float4*)(w + (size_t)row * D_);
    const float4* tr = (const float4*)temb;
    float s = 0.f;
    for (int i = threadIdx.x; i < D_ / 4; i += 128) {
        float4 a = tr[i], c = wr[i];
        a.x *= 1.f / (1.f + __expf(-a.x));
        a.y *= 1.f / (1.f + __expf(-a.y));
        a.z *= 1.f / (1.f + __expf(-a.z));
        a.w *= 1.f / (1.f + __expf(-a.w));
        s += a.x * c.x + a.y * c.y + a.z * c.z + a.w * c.w;
    }
#pragma unroll
    for (int o = 16; o; o >>= 1) s += __shfl_down_sync(0xffffffffu, s, o);
    __shared__ float red[4];
    if ((threadIdx.x & 31) == 0) red[threadIdx.x >> 5] = s;
    __syncthreads();
    if (threadIdx.x == 0) g_emb[row] = red[0] + red[1] + red[2] + red[3] + b[row];
}

// ---------------- layernorm + scale/shift -> nx (bf16 hi/lo) ----------------
__global__ void __launch_bounds__(256) ln_k(const float* __restrict__ x) {
    int row = blockIdx.x, tid = threadIdx.x;
    const float4* xr = (const float4*)(x + (size_t)row * D_);
    float4 v[3];
    float s = 0.f, sq = 0.f;
#pragma unroll
    for (int i = 0; i < 3; i++) {
        v[i] = xr[tid + i * 256];
        s  += v[i].x + v[i].y + v[i].z + v[i].w;
        sq += v[i].x * v[i].x + v[i].y * v[i].y + v[i].z * v[i].z + v[i].w * v[i].w;
    }
    __shared__ float sh1[32], sh2[32];
#pragma unroll
    for (int o = 16; o; o >>= 1) {
        s  += __shfl_down_sync(0xffffffffu, s, o);
        sq += __shfl_down_sync(0xffffffffu, sq, o);
    }
    int w = tid >> 5;
    if ((tid & 31) == 0) { sh1[w] = s; sh2[w] = sq; }
    __syncthreads();
    if (tid < 8) { s = sh1[tid]; sq = sh2[tid]; } else { s = 0.f; sq = 0.f; }
    if (w == 0) {
#pragma unroll
        for (int o = 4; o; o >>= 1) {
            s  += __shfl_down_sync(0xffffffffu, s, o);
            sq += __shfl_down_sync(0xffffffffu, sq, o);
        }
        if (tid == 0) { sh1[0] = s; sh2[0] = sq; }
    }
    __syncthreads();
    float mu = sh1[0] * (1.f / D_);
    float var = sh2[0] * (1.f / D_) - mu * mu;
    float rstd = rsqrtf(var + EPSV);
    const float4* shp = (const float4*)g_emb;
    const float4* scp = (const float4*)(g_emb + D_);
#pragma unroll
    for (int i = 0; i < 3; i++) {
        int idx = tid + i * 256;
        float4 sc = scp[idx], sf = shp[idx], a = v[i], o;
        o.x = (a.x - mu) * rstd * (1.f + sc.x) + sf.x;
        o.y = (a.y - mu) * rstd * (1.f + sc.y) + sf.y;
        o.z = (a.z - mu) * rstd * (1.f + sc.z) + sf.z;
        o.w = (a.w - mu) * rstd * (1.f + sc.w) + sf.w;
        uint32_t h01, l01, h23, l23;
        split2(o.x, o.y, h01, l01);
        split2(o.z, o.w, h23, l23);
        *(uint2*)(g_nx_hi + (size_t)row * D_ + idx * 4) = make_uint2(h01, h23);
        *(uint2*)(g_nx_lo + (size_t)row * D_ + idx * 4) = make_uint2(l01, l23);
    }
}

// ---------------- split-bf16 mma.sync GEMM: C[M,N] = A[M,K] @ B[N,K]^T ----------------
// R8-proven mainloop: CTA 128x256, warp tile 64x64, BK=16, RSTR=24, 3-stage, 1 CTA/SM.
// EPI 0: merged qkv (n0<9216, head scatter) + mlp (gelu -> fused hi/lo).
// EPI 3: split-K partial (blockIdx.z selects K-slice; raw fp32 partial, no bias).
#define RSTR  24                   // row stride in halves (48 B: conflict-free phases)
#define ATILE (128 * RSTR)         // 3072 halves
#define BTILE (256 * RSTR)         // 6144 halves
#define STGH  (2 * ATILE + 2 * BTILE)  // 18432 halves per stage
#define GSMEM (3 * STGH * 2)       // 110592 bytes
#define KSPL  5120                 // K per split-K part for out proj

template <int EPI>
__global__ void __launch_bounds__(256, 1) mgemm_k(
    const __nv_bfloat16* __restrict__ Ah, const __nv_bfloat16* __restrict__ Al,
    const __nv_bfloat16* __restrict__ Bh, const __nv_bfloat16* __restrict__ Bl,
    int Kstride, int kspan, float* __restrict__ C, const float* __restrict__ bias,
    const float* __restrict__ gate, const float* __restrict__ resid,
    const float* __restrict__ mlpb,
    __nv_bfloat16* __restrict__ fhi, __nv_bfloat16* __restrict__ flo) {
    extern __shared__ __align__(16) __nv_bfloat16 sm[];
    const uint32_t sbase = smem_u32(sm);
    const int tid = threadIdx.x, lane = tid & 31, wid = tid >> 5;
    const int wm = wid & 1, wn = wid >> 1;           // 2 x 4 warp grid
    const int m0 = blockIdx.x * 128, n0 = blockIdx.y * 256;
    const int kb = blockIdx.z * kspan;               // K range [kb, kb+kspan)
    const int NKT = kspan >> 4;
    const int K = Kstride;

    auto issue = [&](int stage, int kt) {
        const int k0 = kb + kt * 16;
        const uint32_t sb = sbase + (uint32_t)stage * STGH * 2;
        // 1536 16B chunks: Ah 256, Al 256, Bh 512, Bl 512
#pragma unroll
        for (int it = 0; it < 6; it++) {
            int t = tid + it * 256;
            if (t < 512) {           // A hi/lo
                int half = t >> 8, idx = t & 255;
                int row = idx >> 1, c8 = (idx & 1) * 8;
                const __nv_bfloat16* gp = (half ? Al : Ah) + (size_t)(m0 + row) * K + k0 + c8;
                CP_ASYNC16(sb + (uint32_t)(half * ATILE + row * RSTR + c8) * 2, gp);
            } else {                 // B hi/lo
                int tb = t - 512;
                int half = tb >> 9, idx = tb & 511;
                int row = idx >> 1, c8 = (idx & 1) * 8;
                const __nv_bfloat16* gp = (half ? Bl : Bh) + (size_t)(n0 + row) * K + k0 + c8;
                CP_ASYNC16(sb + (uint32_t)(2 * ATILE + half * BTILE + row * RSTR + c8) * 2, gp);
            }
        }
    };

    float acc[4][8][4];
#pragma unroll
    for (int i = 0; i < 4; i++)
#pragma unroll
        for (int j = 0; j < 8; j++)
#pragma unroll
            for (int u = 0; u < 4; u++) acc[i][j][u] = 0.f;

    issue(0, 0); CP_COMMIT();
    issue(1, 1); CP_COMMIT();

    const uint32_t aoff = (uint32_t)((wm * 64 + (lane & 15)) * RSTR + (lane >> 4) * 8) * 2;
    const uint32_t boff = (uint32_t)((wn * 64 + (lane >> 4) * 8 + (lane & 7)) * RSTR +
                                     ((lane >> 3) & 1) * 8) * 2;

    for (int kt = 0; kt < NKT; kt++) {
        CP_WAIT1();            // stage kt resident
        __syncthreads();       // all warps done reading stage kt-1 (prev iter)
        if (kt + 2 < NKT) issue((kt + 2) % 3, kt + 2);   // overwrites stage kt-1: safe
        CP_COMMIT();

        const uint32_t sb = sbase + (uint32_t)(kt % 3) * (STGH * 2);
        const uint32_t sA = sb + aoff;
        const uint32_t sB = sb + 2 * (ATILE * 2) + boff;
        uint32_t bfh[4][4], bfl[4][4];
#pragma unroll
        for (int jp = 0; jp < 4; jp++) {
            uint32_t bo = sB + jp * (16 * RSTR * 2);
            LDSM4(bfh[jp], bo);
            LDSM4(bfl[jp], bo + BTILE * 2);
        }
#pragma unroll
        for (int i = 0; i < 4; i++) {
            uint32_t ah[4], al[4];
            uint32_t ao = sA + i * (16 * RSTR * 2);
            LDSM4(ah, ao);
            LDSM4(al, ao + ATILE * 2);
#pragma unroll
            for (int j = 0; j < 8; j++) MMA_BF16(acc[i][j], ah, bfh[j >> 1] + (j & 1) * 2);
#pragma unroll
            for (int j = 0; j < 8; j++) MMA_BF16(acc[i][j], ah, bfl[j >> 1] + (j & 1) * 2);
#pragma unroll
            for (int j = 0; j < 8; j++) MMA_BF16(acc[i][j], al, bfh[j >> 1] + (j & 1) * 2);
        }
    }

    // ---- epilogue ----
    int sec = 0, hq = 0;
    const float* bsel = bias;
    const bool is_qkv = (EPI == 0) && (n0 < 9216);
    if (is_qkv) {
        sec = blockIdx.y / 12;          // 12 CTAs of 256 cols per 3072-col section
        hq = blockIdx.y % 12;           // 2 heads per CTA
        bsel = (sec == 0) ? bias : (sec == 1) ? gate : resid;
    }
    float* Cz = C;
    if (EPI == 3) Cz = C + (size_t)blockIdx.z * S_ * D_;
#pragma unroll
    for (int i = 0; i < 4; i++) {
        int r0 = m0 + wm * 64 + i * 16 + (lane >> 2);
#pragma unroll
        for (int j = 0; j < 8; j++) {
            int cloc = wn * 64 + j * 8 + (lane & 3) * 2;   // 0..255 within tile
            int cg = n0 + cloc;
            if (EPI == 0) {
                if (is_qkv) {
                    int head = hq * 2 + (cloc >> 7);
                    int ch = cloc & 127;
                    float b0 = bsel[head * 128 + ch], b1 = bsel[head * 128 + ch + 1];
                    float v00 = acc[i][j][0] + b0, v01 = acc[i][j][1] + b1;
                    float v10 = acc[i][j][2] + b0, v11 = acc[i][j][3] + b1;
                    size_t base = (((size_t)sec * NH_ + head) * S_ + r0) * DH_ + ch;
                    *(float2*)(C + base) = make_float2(v00, v01);
                    *(float2*)(C + base + 8 * DH_) = make_float2(v10, v11);
                } else {
                    int col = cg - 9216;
                    float b0 = mlpb[col], b1 = mlpb[col + 1];
                    float v00 = gelu_tanh(acc[i][j][0] + b0), v01 = gelu_tanh(acc[i][j][1] + b1);
                    float v10 = gelu_tanh(acc[i][j][2] + b0), v11 = gelu_tanh(acc[i][j][3] + b1);
                    uint32_t h0, l0, h1, l1;
                    split2(v00, v01, h0, l0);
                    split2(v10, v11, h1, l1);
                    size_t base = (size_t)r0 * FD_ + D_ + col;
                    *(uint32_t*)(fhi + base) = h0;
                    *(uint32_t*)(flo + base) = l0;
                    *(uint32_t*)(fhi + base + (size_t)8 * FD_) = h1;
                    *(uint32_t*)(flo + base + (size_t)8 * FD_) = l1;
                }
            } else {   // EPI == 3: raw partial
                size_t base = (size_t)r0 * D_ + cg;
                *(float2*)(Cz + base) = make_float2(acc[i][j][0], acc[i][j][1]);
                *(float2*)(Cz + base + 8 * D_) = make_float2(acc[i][j][2], acc[i][j][3]);
            }
        }
    }
}

// ---------------- split-K reduce + bias + gate + residual ----------------
__global__ void __launch_bounds__(256) redout_k(const float* __restrict__ bias,
                                                const float* __restrict__ gate,
                                                const float* __restrict__ resid,
                                                float* __restrict__ out) {
    int i = blockIdx.x * 256 + threadIdx.x;              // float4 index
    if (i >= (int)((size_t)S_ * D_ / 4)) return;
    int col4 = (i % (D_ / 4)) * 4;
    const float4* p0 = (const float4*)g_part + i;
    const float4* p1 = (const float4*)(g_part + (size_t)S_ * D_) + i;
    const float4* p2 = (const float4*)(g_part + (size_t)2 * S_ * D_) + i;
    float4 a = *p0, b = *p1, c = *p2;
    float4 bs = *(const float4*)(bias + col4);
    float4 gt = *(const float4*)(gate + col4);
    float4 rv = ((const float4*)resid)[i];
    float4 o;
    o.x = rv.x + gt.x * (a.x + b.x + c.x + bs.x);
    o.y = rv.y + gt.y * (a.y + b.y + c.y + bs.y);
    o.z = rv.z + gt.z * (a.z + b.z + c.z + bs.z);
    o.w = rv.w + gt.w * (a.w + b.w + c.w + bs.w);
    ((float4*)out)[i] = o;
}

// ---------------- per-head RMSNorm + RoPE + bf16 hi/lo split (q,k,v) ----------------
__global__ void __launch_bounds__(128) rmsrope_k(const float* __restrict__ cosb,
                                                 const float* __restrict__ sinb,
                                                 const float* __restrict__ qrw,
                                                 const float* __restrict__ krw) {
    int s = blockIdx.x, h = blockIdx.y, j = threadIdx.x;
    size_t idx = ((size_t)h * S_ + s) * DH_ + j;
    float qv = g_qkv[idx], kv = g_qkv[NHSD + idx], vv = g_qkv[2 * NHSD + idx];
    float q2 = qv * qv, k2 = kv * kv;
#pragma unroll
    for (int o = 16; o; o >>= 1) {
        q2 += __shfl_xor_sync(0xffffffffu, q2, o);
        k2 += __shfl_xor_sync(0xffffffffu, k2, o);
    }
    __shared__ float sq[4], sk[4];
    int w = j >> 5;
    if ((j & 31) == 0) { sq[w] = q2; sk[w] = k2; }
    __syncthreads();
    float qsum = sq[0] + sq[1] + sq[2] + sq[3];
    float ksum = sk[0] + sk[1] + sk[2] + sk[3];
    float qr = rsqrtf(qsum * (1.f / DH_) + EPSV);
    float kr = rsqrtf(ksum * (1.f / DH_) + EPSV);
    qv *= qr * qrw[j];
    kv *= kr * krw[j];
    float qp = __shfl_xor_sync(0xffffffffu, qv, 1);
    float kp = __shfl_xor_sync(0xffffffffu, kv, 1);
    float qrot = (j & 1) ? qp : -qp;
    float krot = (j & 1) ? kp : -kp;
    float c = cosb[s * DH_ + j], sn = sinb[s * DH_ + j];
    float qf = qv * c + qrot * sn;
    float kf = kv * c + krot * sn;
    __nv_bfloat16 qh = __float2bfloat16(qf);
    __nv_bfloat16 kh = __float2bfloat16(kf);
    __nv_bfloat16 vh = __float2bfloat16(vv);
    g_qsh[idx] = qh; g_qsl[idx] = __float2bfloat16(qf - __bfloat162float(qh));
    g_ksh[idx] = kh; g_ksl[idx] = __float2bfloat16(kf - __bfloat162float(kh));
    g_vsh[idx] = vh; g_vsl[idx] = __float2bfloat16(vv - __bfloat162float(vh));
}

// ---------------- tensor-core flash attention ----------------
// 8 warps, q tile 128 (16 rows/warp), kv tile 64, split-bf16 3-pass QK^T and P.V
#define ASTR   136
#define QHALF  (128 * ASTR)
#define KVHALF (64 * ASTR)
#define STGHALF (4 * KVHALF)
#define ATT2_SMEM ((2 * QHALF + 2 * STGHALF) * 2)   // 208896 bytes

__global__ void __launch_bounds__(256, 1) attn2_k(__nv_bfloat16* __restrict__ fh,
                                                  __nv_bfloat16* __restrict__ fl) {
    extern __shared__ __align__(16) char smraw[];
    const uint32_t sb = smem_u32(smraw);
    const int tid = threadIdx.x, lane = tid & 31, wid = tid >> 5;
    const int h = blockIdx.y, qt = blockIdx.x;
    const __nv_bfloat16* Qgh = g_qsh + ((size_t)h * S_ + (size_t)qt * 128) * DH_;
    const __nv_bfloat16* Qgl = g_qsl + ((size_t)h * S_ + (size_t)qt * 128) * DH_;
    const __nv_bfloat16* Kgh = g_ksh + (size_t)h * S_ * DH_;
    const __nv_bfloat16* Kgl = g_ksl + (size_t)h * S_ * DH_;
    const __nv_bfloat16* Vgh = g_vsh + (size_t)h * S_ * DH_;
    const __nv_bfloat16* Vgl = g_vsl + (size_t)h * S_ * DH_;

    const uint32_t uQh = sb, uQl = sb + QHALF * 2;
    const uint32_t uStage = sb + 2 * QHALF * 2;

    auto issueKV = [&](int st, int kt) {
        uint32_t base = uStage + (uint32_t)st * STGHALF * 2;
#pragma unroll
        for (int it = 0; it < 16; it++) {
            int cidx = tid + it * 256;
            int mat = cidx >> 10, rem = cidx & 1023;
            int row = rem >> 4, c8 = rem & 15;
            const __nv_bfloat16* src;
            if (mat == 0) src = Kgh; else if (mat == 1) src = Kgl;
            else if (mat == 2) src = Vgh; else src = Vgl;
            CP_ASYNC16(base + (uint32_t)(mat * KVHALF + row * ASTR + c8 * 8) * 2,
                       src + ((size_t)(kt * 64 + row)) * DH_ + c8 * 8);
        }
    };
#pragma unroll
    for (int it = 0; it < 8; it++) {
        int cidx = tid + it * 256;
        int row = cidx >> 4, c8 = cidx & 15;
        CP_ASYNC16(uQh + (uint32_t)(row * ASTR + c8 * 8) * 2, Qgh + (size_t)row * DH_ + c8 * 8);
        CP_ASYNC16(uQl + (uint32_t)(row * ASTR + c8 * 8) * 2, Qgl + (size_t)row * DH_ + c8 * 8);
    }
    issueKV(0, 0); CP_COMMIT();
    issueKV(1, 1); CP_COMMIT();

    float o[16][4];
#pragma unroll
    for (int n = 0; n < 16; n++)
#pragma unroll
        for (int u = 0; u < 4; u++) o[n][u] = 0.f;
    float m0 = -3.0e38f, m1 = -3.0e38f, l0 = 0.f, l1 = 0.f;
    const int r0 = wid * 16;
    const float scale = 0.08838834764831845f;

    for (int kt = 0; kt < S_ / 64; kt++) {
        CP_WAIT1();
        __syncthreads();
        const uint32_t base = uStage + (uint32_t)(kt & 1) * STGHALF * 2;

        float sc[8][4];
#pragma unroll
        for (int n = 0; n < 8; n++)
#pragma unroll
            for (int u = 0; u < 4; u++) sc[n][u] = 0.f;
#pragma unroll
        for (int kc = 0; kc < 8; kc++) {
            uint32_t qh4[4], ql4[4];
            uint32_t qoff = (uint32_t)((r0 + (lane & 15)) * ASTR + kc * 16 + (lane >> 4) * 8) * 2;
            LDSM4(qh4, uQh + qoff);
            LDSM4(ql4, uQl + qoff);
            uint32_t kh4[4][4], kl4[4][4];
#pragma unroll
            for (int jp = 0; jp < 4; jp++) {
                uint32_t koff = base + (uint32_t)(((2 * jp + (lane >> 4)) * 8 + (lane & 7)) * ASTR +
                                                  kc * 16 + ((lane >> 3) & 1) * 8) * 2;
                LDSM4(kh4[jp], koff);
                LDSM4(kl4[jp], koff + KVHALF * 2);
            }
#pragma unroll
            for (int jp = 0; jp < 4; jp++) {
                MMA_BF16(sc[2 * jp],     qh4, kh4[jp]);
                MMA_BF16(sc[2 * jp + 1], qh4, kh4[jp] + 2);
            }
#pragma unroll
            for (int jp = 0; jp < 4; jp++) {
                MMA_BF16(sc[2 * jp],     qh4, kl4[jp]);
                MMA_BF16(sc[2 * jp + 1], qh4, kl4[jp] + 2);
            }
#pragma unroll
            for (int jp = 0; jp < 4; jp++) {
                MMA_BF16(sc[2 * jp],     ql4, kh4[jp]);
                MMA_BF16(sc[2 * jp + 1], ql4, kh4[jp] + 2);
            }
        }
        float mx0 = -3.0e38f, mx1 = -3.0e38f;
#pragma unroll
        for (int n = 0; n < 8; n++) {
            sc[n][0] *= scale; sc[n][1] *= scale; sc[n][2] *= scale; sc[n][3] *= scale;
            mx0 = fmaxf(mx0, fmaxf(sc[n][0], sc[n][1]));
            mx1 = fmaxf(mx1, fmaxf(sc[n][2], sc[n][3]));
        }
        mx0 = fmaxf(mx0, __shfl_xor_sync(0xffffffffu, mx0, 1));
        mx0 = fmaxf(mx0, __shfl_xor_sync(0xffffffffu, mx0, 2));
        mx1 = fmaxf(mx1, __shfl_xor_sync(0xffffffffu, mx1, 1));
        mx1 = fmaxf(mx1, __shfl_xor_sync(0xffffffffu, mx1, 2));
        float m0n = fmaxf(m0, mx0), m1n = fmaxf(m1, mx1);
        float c0 = __expf(m0 - m0n), c1 = __expf(m1 - m1n);
        m0 = m0n; m1 = m1n;
        uint32_t pah[4][4], pal[4][4];
        float s0 = 0.f, s1 = 0.f;
#pragma unroll
        for (int t = 0; t < 4; t++) {
            float p00 = __expf(sc[2 * t][0] - m0n),     p01 = __expf(sc[2 * t][1] - m0n);
            float p02 = __expf(sc[2 * t][2] - m1n),     p03 = __expf(sc[2 * t][3] - m1n);
            float p10 = __expf(sc[2 * t + 1][0] - m0n), p11 = __expf(sc[2 * t + 1][1] - m0n);
            float p12 = __expf(sc[2 * t + 1][2] - m1n), p13 = __expf(sc[2 * t + 1][3] - m1n);
            s0 += p00 + p01 + p10 + p11;
            s1 += p02 + p03 + p12 + p13;
            split2(p00, p01, pah[t][0], pal[t][0]);
            split2(p02, p03, pah[t][1], pal[t][1]);
            split2(p10, p11, pah[t][2], pal[t][2]);
            split2(p12, p13, pah[t][3], pal[t][3]);
        }
        s0 += __shfl_xor_sync(0xffffffffu, s0, 1);
        s0 += __shfl_xor_sync(0xffffffffu, s0, 2);
        s1 += __shfl_xor_sync(0xffffffffu, s1, 1);
        s1 += __shfl_xor_sync(0xffffffffu, s1, 2);
        l0 = l0 * c0 + s0;
        l1 = l1 * c1 + s1;
#pragma unroll
        for (int n = 0; n < 16; n++) {
            o[n][0] *= c0; o[n][1] *= c0; o[n][2] *= c1; o[n][3] *= c1;
        }
#pragma unroll
        for (int t = 0; t < 4; t++) {
#pragma unroll
            for (int dp = 0; dp < 8; dp += 2) {
                uint32_t vh4[2][4], vl4[2][4];
#pragma unroll
                for (int u = 0; u < 2; u++) {
                    uint32_t voff = base + (uint32_t)(2 * KVHALF +
                                    (t * 16 + (lane & 7) + ((lane & 8) ? 8 : 0)) * ASTR +
                                    (dp + u) * 16 + ((lane & 16) ? 8 : 0)) * 2;
                    LDSM4T(vh4[u], voff);
                    LDSM4T(vl4[u], voff + KVHALF * 2);
                }
#pragma unroll
                for (int u = 0; u < 2; u++) {
                    MMA_BF16(o[2 * (dp + u)],     pah[t], vh4[u]);
                    MMA_BF16(o[2 * (dp + u) + 1], pah[t], vh4[u] + 2);
                }
#pragma unroll
                for (int u = 0; u < 2; u++) {
                    MMA_BF16(o[2 * (dp + u)],     pah[t], vl4[u]);
                    MMA_BF16(o[2 * (dp + u) + 1], pah[t], vl4[u] + 2);
                }
#pragma unroll
                for (int u = 0; u < 2; u++) {
                    MMA_BF16(o[2 * (dp + u)],     pal[t], vh4[u]);
                    MMA_BF16(o[2 * (dp + u) + 1], pal[t], vh4[u] + 2);
                }
            }
        }
        __syncthreads();
        if (kt + 2 < S_ / 64) issueKV(kt & 1, kt + 2);
        CP_COMMIT();
    }
    float inv0 = 1.f / l0, inv1 = 1.f / l1;
    int ra = qt * 128 + r0 + (lane >> 2);
    int rb = ra + 8;
    int cb = h * DH_ + (lane & 3) * 2;
#pragma unroll
    for (int dn = 0; dn < 16; dn++) {
        uint32_t hh, ll;
        split2(o[dn][0] * inv0, o[dn][1] * inv0, hh, ll);
        *(uint32_t*)(fh + (size_t)ra * FD_ + cb + dn * 8) = hh;
        *(uint32_t*)(fl + (size_t)ra * FD_ + cb + dn * 8) = ll;
        split2(o[dn][2] * inv1, o[dn][3] * inv1, hh, ll);
        *(uint32_t*)(fh + (size_t)rb * FD_ + cb + dn * 8) = hh;
        *(uint32_t*)(fl + (size_t)rb * FD_ + cb + dn * 8) = ll;
    }
}

// ---------------- launch ----------------
extern "C" void kernel_launch(void* const* d_in, const int* in_sizes, int n_in,
                              void* d_out, int out_size) {
    (void)in_sizes; (void)n_in; (void)out_size;
    const float* hidden = (const float*)d_in[0];
    const float* temb   = (const float*)d_in[1];
    const float* cosb   = (const float*)d_in[2];
    const float* sinb   = (const float*)d_in[3];
    const float* norm_w = (const float*)d_in[4];
    const float* norm_b = (const float*)d_in[5];
    const float* qw = (const float*)d_in[6];
    const float* qb = (const float*)d_in[7];
    const float* kw = (const float*)d_in[8];
    const float* kb = (const float*)d_in[9];
    const float* vw = (const float*)d_in[10];
    const float* vb = (const float*)d_in[11];
    const float* qrw = (const float*)d_in[12];
    const float* krw = (const float*)d_in[13];
    const float* mlp_w = (const float*)d_in[14];
    const float* mlp_b = (const float*)d_in[15];
    const float* out_w = (const float*)d_in[16];
    const float* out_b = (const float*)d_in[17];
    float* out = (float*)d_out;

    void *p_qkv, *p_fh, *p_fl, *p_emb, *p_wh, *p_wl, *p_nxh, *p_nxl, *p_part;
    cudaGetSymbolAddress(&p_nxh, g_nx_hi);
    cudaGetSymbolAddress(&p_nxl, g_nx_lo);
    cudaGetSymbolAddress(&p_qkv, g_qkv);
    cudaGetSymbolAddress(&p_fh, g_f_hi);
    cudaGetSymbolAddress(&p_fl, g_f_lo);
    cudaGetSymbolAddress(&p_emb, g_emb);
    cudaGetSymbolAddress(&p_wh, g_w_hi);
    cudaGetSymbolAddress(&p_wl, g_w_lo);
    cudaGetSymbolAddress(&p_part, g_part);
    __nv_bfloat16* wh = (__nv_bfloat16*)p_wh;
    __nv_bfloat16* wl = (__nv_bfloat16*)p_wl;
    const __nv_bfloat16* nxh = (const __nv_bfloat16*)p_nxh;
    const __nv_bfloat16* nxl = (const __nv_bfloat16*)p_nxl;
    const __nv_bfloat16* fh = (const __nv_bfloat16*)p_fh;
    const __nv_bfloat16* fl = (const __nv_bfloat16*)p_fl;

    cudaFuncSetAttribute(mgemm_k<0>, cudaFuncAttributeMaxDynamicSharedMemorySize, GSMEM);
    cudaFuncSetAttribute(mgemm_k<3>, cudaFuncAttributeMaxDynamicSharedMemorySize, GSMEM);
    cudaFuncSetAttribute(attn2_k, cudaFuncAttributeMaxDynamicSharedMemorySize, ATT2_SMEM);

    dim3 gfused(S_ / 128, (9216 + M_) / 256);   // 16 x 84, fused q/k/v + mlp
    dim3 gout(S_ / 128, D_ / 256, 3);           // 16 x 12 x 3 split-K

    convall_k<<<dim3((WSEG / 4 + 1023) / 1024, 7), 256>>>(qw, kw, vw, mlp_w, wh, wl);      // 0
    emb_k<<<3 * D_, 128>>>(temb, norm_w, norm_b);                                          // 1
    ln_k<<<S_, 256>>>(hidden);                                                             // 2
    mgemm_k<0><<<gfused, 256, GSMEM>>>(nxh, nxl, wh, wl, D_, D_,                           // 3
                                       (float*)p_qkv, qb, kb, vb, mlp_b,
                                       (__nv_bfloat16*)p_fh, (__nv_bfloat16*)p_fl);
    rmsrope_k<<<dim3(S_, NH_), 128>>>(cosb, sinb, qrw, krw);                               // 4
    attn2_k<<<dim3(S_ / 128, NH_), 256, ATT2_SMEM>>>((__nv_bfloat16*)p_fh,                 // 5
                                                     (__nv_bfloat16*)p_fl);
    convw_k<<<(47185920 / 4 + 1023) / 1024, 256>>>(out_w, wh + WOFF_OUT, wl + WOFF_OUT,    // 6
                                                   47185920 / 4);
    mgemm_k<3><<<gout, 256, GSMEM>>>(fh, fl, wh + WOFF_OUT, wl + WOFF_OUT, FD_, KSPL,      // 7
                                     (float*)p_part, nullptr, nullptr, nullptr, nullptr,
                                     nullptr, nullptr);
    redout_k<<<((S_ * D_ / 4) + 255) / 256, 256>>>(out_b, (const float*)p_emb + 2 * D_,    // 8
                                                   hidden, out);
}

// round 13
// speedup vs baseline: 1.7179x; 1.3390x over previous
#include <cuda_runtime.h>
#include <cuda.h>
#include <cuda_bf16.h>
#include <cstdint>

#define S_   2048
#define D_   3072
#define NH_  24
#define DH_  128
#define M_   12288
#define FD_  15360   // D_ + M_
#define NHSD ((size_t)NH_ * S_ * DH_)
#define EPSV 1e-6f

// ---------------- scratch (device globals: no allocation allowed) ----------------
static __device__ __align__(16) float g_emb[3 * D_];
static __device__ __align__(16) __nv_bfloat16 g_nx_hi[(size_t)S_ * D_];
static __device__ __align__(16) __nv_bfloat16 g_nx_lo[(size_t)S_ * D_];
static __device__ __align__(16) float g_qkv[3 * NHSD];   // q,k,v sections
// split-bf16 q/k/v for tensor-core attention
static __device__ __align__(16) __nv_bfloat16 g_qsh[NHSD];
static __device__ __align__(16) __nv_bfloat16 g_qsl[NHSD];
static __device__ __align__(16) __nv_bfloat16 g_ksh[NHSD];
static __device__ __align__(16) __nv_bfloat16 g_ksl[NHSD];
static __device__ __align__(16) __nv_bfloat16 g_vsh[NHSD];
static __device__ __align__(16) __nv_bfloat16 g_vsl[NHSD];
static __device__ __align__(16) __nv_bfloat16 g_f_hi[(size_t)S_ * FD_];
static __device__ __align__(16) __nv_bfloat16 g_f_lo[(size_t)S_ * FD_];
// split-K partials for out projection (3 x S x D fp32)
static __device__ __align__(16) float g_part[(size_t)3 * S_ * D_];
// weights split into one big hi / lo buffer; 12 equal 9.4M segments:
// 0-2 q/k/v, 3-6 mlp quarters, 7-11 out fifths
#define WOFF_OUT 66060288
#define WTOT     113246208
#define WSEG     9437184
static __device__ __align__(16) __nv_bfloat16 g_w_hi[(size_t)WTOT];
static __device__ __align__(16) __nv_bfloat16 g_w_lo[(size_t)WTOT];

// ---------------- PTX helpers (sm_80-level: valid on base sm_103 target) ----------------
__device__ __forceinline__ uint32_t smem_u32(const void* p) {
    uint32_t a;
    asm("{ .reg .u64 t; cvta.to.shared.u64 t, %1; cvt.u32.u64 %0, t; }" : "=r"(a) : "l"(p));
    return a;
}
#define CP_ASYNC16(saddr, gptr) \
    asm volatile("cp.async.cg.shared.global [%0], [%1], 16;" :: "r"(saddr), "l"(gptr) : "memory")
#define CP_COMMIT() asm volatile("cp.async.commit_group;" ::: "memory")
#define CP_WAIT1()  asm volatile("cp.async.wait_group 1;" ::: "memory")

#define LDSM4(r, addr) \
    asm volatile("ldmatrix.sync.aligned.m8n8.x4.shared.b16 {%0,%1,%2,%3}, [%4];" \
                 : "=r"((r)[0]), "=r"((r)[1]), "=r"((r)[2]), "=r"((r)[3]) : "r"(addr))
#define LDSM4T(r, addr) \
    asm volatile("ldmatrix.sync.aligned.m8n8.x4.trans.shared.b16 {%0,%1,%2,%3}, [%4];" \
                 : "=r"((r)[0]), "=r"((r)[1]), "=r"((r)[2]), "=r"((r)[3]) : "r"(addr))
#define MMA_BF16(d, a, b) \
    asm volatile("mma.sync.aligned.m16n8k16.row.col.f32.bf16.bf16.f32 " \
                 "{%0,%1,%2,%3}, {%4,%5,%6,%7}, {%8,%9}, {%0,%1,%2,%3};" \
                 : "+f"((d)[0]), "+f"((d)[1]), "+f"((d)[2]), "+f"((d)[3]) \
                 : "r"((a)[0]), "r"((a)[1]), "r"((a)[2]), "r"((a)[3]), \
                   "r"((b)[0]), "r"((b)[1]))

// ---------------- small helpers ----------------
__device__ __forceinline__ float gelu_tanh(float x) {
    float u = 0.7978845608028654f * (x + 0.044715f * x * x * x);
    float t = __expf(2.f * u);
    float th = 1.f - 2.f / (t + 1.f);
    return 0.5f * x * (1.f + th);
}
__device__ __forceinline__ void split2(float a, float b, uint32_t& h, uint32_t& l) {
    __nv_bfloat162 hb = __floats2bfloat162_rn(a, b);
    float2 hf = __bfloat1622float2(hb);
    __nv_bfloat162 lb = __floats2bfloat162_rn(a - hf.x, b - hf.y);
    h = *(uint32_t*)&hb;
    l = *(uint32_t*)&lb;
}

// ---------------- all 12 weight segments -> bf16 hi/lo in one launch ----------------
__global__ void __launch_bounds__(256) convall_k(const float* __restrict__ q,
                                                 const float* __restrict__ k,
                                                 const float* __restrict__ v,
                                                 const float* __restrict__ mlp,
                                                 const float* __restrict__ ow,
                                                 __nv_bfloat16* __restrict__ hi,
                                                 __nv_bfloat16* __restrict__ lo) {
    const int seg = blockIdx.y;
    const float* src;
    if (seg == 0) src = q;
    else if (seg == 1) src = k;
    else if (seg == 2) src = v;
    else if (seg < 7) src = mlp + (size_t)(seg - 3) * WSEG;
    else src = ow + (size_t)(seg - 7) * WSEG;
    size_t doff = (size_t)seg * WSEG;
    const int n4seg = WSEG / 4;
    int base = blockIdx.x * 1024 + threadIdx.x;
#pragma unroll
    for (int u = 0; u < 4; u++) {
        int i = base + u * 256;
        if (i < n4seg) {
            float4 w4 = ((const float4*)src)[i];
            uint32_t h01, l01, h23, l23;
            split2(w4.x, w4.y, h01, l01);
            split2(w4.z, w4.w, h23, l23);
            *(uint2*)(hi + doff + (size_t)i * 4) = make_uint2(h01, h23);
            *(uint2*)(lo + doff + (size_t)i * 4) = make_uint2(l01, l23);
        }
    }
}

// ---------------- emb = silu(temb) @ norm_w.T + norm_b ----------------
__global__ void __launch_bounds__(128) emb_k(const float* __restrict__ temb,
                                             const float* __restrict__ w,
                                             const float* __restrict__ b) {
    int row = blockIdx.x;
    const float4* wr = (const float4*)(w + (size_t)row * D_);
    const float4* tr = (const float4*)temb;
    float s = 0.f;
    for (int i = threadIdx.x; i < D_ / 4; i += 128) {
        float4 a = tr[i], c = wr[i];
        a.x *= 1.f / (1.f + __expf(-a.x));
        a.y *= 1.f / (1.f + __expf(-a.y));
        a.z *= 1.f / (1.f + __expf(-a.z));
        a.w *= 1.f / (1.f + __expf(-a.w));
        s += a.x * c.x + a.y * c.y + a.z * c.z + a.w * c.w;
    }
#pragma unroll
    for (int o = 16; o; o >>= 1) s += __shfl_down_sync(0xffffffffu, s, o);
    __shared__ float red[4];
    if ((threadIdx.x & 31) == 0) red[threadIdx.x >> 5] = s;
    __syncthreads();
    if (threadIdx.x == 0) g_emb[row] = red[0] + red[1] + red[2] + red[3] + b[row];
}

// ---------------- layernorm + scale/shift -> nx (bf16 hi/lo) ----------------
__global__ void __launch_bounds__(256) ln_k(const float* __restrict__ x) {
    int row = blockIdx.x, tid = threadIdx.x;
    const float4* xr = (const float4*)(x + (size_t)row * D_);
    float4 v[3];
    float s = 0.f, sq = 0.f;
#pragma unroll
    for (int i = 0; i < 3; i++) {
        v[i] = xr[tid + i * 256];
        s  += v[i].x + v[i].y + v[i].z + v[i].w;
        sq += v[i].x * v[i].x + v[i].y * v[i].y + v[i].z * v[i].z + v[i].w * v[i].w;
    }
    __shared__ float sh1[32], sh2[32];
#pragma unroll
    for (int o = 16; o; o >>= 1) {
        s  += __shfl_down_sync(0xffffffffu, s, o);
        sq += __shfl_down_sync(0xffffffffu, sq, o);
    }
    int w = tid >> 5;
    if ((tid & 31) == 0) { sh1[w] = s; sh2[w] = sq; }
    __syncthreads();
    if (tid < 8) { s = sh1[tid]; sq = sh2[tid]; } else { s = 0.f; sq = 0.f; }
    if (w == 0) {
#pragma unroll
        for (int o = 4; o; o >>= 1) {
            s  += __shfl_down_sync(0xffffffffu, s, o);
            sq += __shfl_down_sync(0xffffffffu, sq, o);
        }
        if (tid == 0) { sh1[0] = s; sh2[0] = sq; }
    }
    __syncthreads();
    float mu = sh1[0] * (1.f / D_);
    float var = sh2[0] * (1.f / D_) - mu * mu;
    float rstd = rsqrtf(var + EPSV);
    const float4* shp = (const float4*)g_emb;
    const float4* scp = (const float4*)(g_emb + D_);
#pragma unroll
    for (int i = 0; i < 3; i++) {
        int idx = tid + i * 256;
        float4 sc = scp[idx], sf = shp[idx], a = v[i], o;
        o.x = (a.x - mu) * rstd * (1.f + sc.x) + sf.x;
        o.y = (a.y - mu) * rstd * (1.f + sc.y) + sf.y;
        o.z = (a.z - mu) * rstd * (1.f + sc.z) + sf.z;
        o.w = (a.w - mu) * rstd * (1.f + sc.w) + sf.w;
        uint32_t h01, l01, h23, l23;
        split2(o.x, o.y, h01, l01);
        split2(o.z, o.w, h23, l23);
        *(uint2*)(g_nx_hi + (size_t)row * D_ + idx * 4) = make_uint2(h01, h23);
        *(uint2*)(g_nx_lo + (size_t)row * D_ + idx * 4) = make_uint2(l01, l23);
    }
}

// ---------------- split-bf16 mma.sync GEMM: C[M,N] = A[M,K] @ B[N,K]^T ----------------
// CTA tile 128x128, 128 threads (2x2 warps of 64x64), BK=16, RSTR=24, 3-stage,
// __launch_bounds__(128,2) => 2 independent CTAs/SM fill each other's sync bubbles.
// EPI 0: merged qkv (y<72, head scatter) + mlp (gelu -> fused hi/lo).
// EPI 3: split-K partial for out proj (blockIdx.z = K slice).
#define RSTR  24                   // row stride in halves (48 B, conflict-clean)
#define TIL   (128 * RSTR)         // 3072 halves per matrix tile
#define STGH  (4 * TIL)            // Ah,Al,Bh,Bl per stage = 12288 halves
#define GSMEM (3 * STGH * 2)       // 73728 bytes
#define KSPL  5120                 // K per split-K slice for out proj

template <int EPI>
__global__ void __launch_bounds__(128, 2) mgemm_k(
    const __nv_bfloat16* __restrict__ Ah, const __nv_bfloat16* __restrict__ Al,
    const __nv_bfloat16* __restrict__ Bh, const __nv_bfloat16* __restrict__ Bl,
    int Kstride, int kspan, float* __restrict__ C, const float* __restrict__ bias,
    const float* __restrict__ gate, const float* __restrict__ resid,
    const float* __restrict__ mlpb,
    __nv_bfloat16* __restrict__ fhi, __nv_bfloat16* __restrict__ flo) {
    extern __shared__ __align__(16) __nv_bfloat16 sm[];
    const uint32_t sbase = smem_u32(sm);
    const int tid = threadIdx.x, lane = tid & 31, wid = tid >> 5;
    const int wm = wid & 1, wn = wid >> 1;           // 2 x 2 warp grid
    const int m0 = blockIdx.x * 128, n0 = blockIdx.y * 128;
    const int kb = blockIdx.z * kspan;
    const int NKT = kspan >> 4;
    const int K = Kstride;

    auto issue = [&](int stage, int kt) {
        const int k0 = kb + kt * 16;
        const uint32_t sb = sbase + (uint32_t)stage * STGH * 2;
        // 1024 16B chunks (4 matrices x 128 rows x 2 chunks), 128 threads, 8 iters
#pragma unroll
        for (int it = 0; it < 8; it++) {
            int t = tid + it * 128;
            int mat = t >> 8, idx = t & 255;
            int row = idx >> 1, c8 = (idx & 1) * 8;
            const __nv_bfloat16* g;
            int grow;
            if (mat == 0)      { g = Ah; grow = m0 + row; }
            else if (mat == 1) { g = Al; grow = m0 + row; }
            else if (mat == 2) { g = Bh; grow = n0 + row; }
            else               { g = Bl; grow = n0 + row; }
            CP_ASYNC16(sb + (uint32_t)(mat * TIL + row * RSTR + c8) * 2,
                       g + (size_t)grow * K + k0 + c8);
        }
    };

    float acc[4][8][4];
#pragma unroll
    for (int i = 0; i < 4; i++)
#pragma unroll
        for (int j = 0; j < 8; j++)
#pragma unroll
            for (int u = 0; u < 4; u++) acc[i][j][u] = 0.f;

    issue(0, 0); CP_COMMIT();
    issue(1, 1); CP_COMMIT();

    const uint32_t aoff = (uint32_t)((wm * 64 + (lane & 15)) * RSTR + (lane >> 4) * 8) * 2;
    const uint32_t boff = (uint32_t)((wn * 64 + (lane >> 4) * 8 + (lane & 7)) * RSTR +
                                     ((lane >> 3) & 1) * 8) * 2;

    for (int kt = 0; kt < NKT; kt++) {
        CP_WAIT1();            // stage kt resident
        __syncthreads();       // all warps done reading stage kt-1
        if (kt + 2 < NKT) issue((kt + 2) % 3, kt + 2);
        CP_COMMIT();

        const uint32_t sb = sbase + (uint32_t)(kt % 3) * (STGH * 2);
        const uint32_t sA = sb + aoff;
        const uint32_t sB = sb + 2 * (TIL * 2) + boff;
        uint32_t bfh[4][4], bfl[4][4];
#pragma unroll
        for (int jp = 0; jp < 4; jp++) {
            uint32_t bo = sB + jp * (16 * RSTR * 2);
            LDSM4(bfh[jp], bo);
            LDSM4(bfl[jp], bo + TIL * 2);
        }
#pragma unroll
        for (int i = 0; i < 4; i++) {
            uint32_t ah[4], al[4];
            uint32_t ao = sA + i * (16 * RSTR * 2);
            LDSM4(ah, ao);
            LDSM4(al, ao + TIL * 2);
#pragma unroll
            for (int j = 0; j < 8; j++) MMA_BF16(acc[i][j], ah, bfh[j >> 1] + (j & 1) * 2);
#pragma unroll
            for (int j = 0; j < 8; j++) MMA_BF16(acc[i][j], ah, bfl[j >> 1] + (j & 1) * 2);
#pragma unroll
            for (int j = 0; j < 8; j++) MMA_BF16(acc[i][j], al, bfh[j >> 1] + (j & 1) * 2);
        }
    }

    // ---- epilogue ----
    int sec = 0, head = 0;
    const float* bsel = bias;
    const bool is_qkv = (EPI == 0) && (blockIdx.y < 72);
    if (is_qkv) {
        sec = blockIdx.y / NH_;
        head = blockIdx.y % NH_;
        bsel = (sec == 0) ? bias : (sec == 1) ? gate : resid;
    }
    float* Cz = C;
    if (EPI == 3) Cz = C + (size_t)blockIdx.z * S_ * D_;
#pragma unroll
    for (int i = 0; i < 4; i++) {
        int r0 = m0 + wm * 64 + i * 16 + (lane >> 2);
#pragma unroll
        for (int j = 0; j < 8; j++) {
            int cloc = wn * 64 + j * 8 + (lane & 3) * 2;   // 0..127 within tile
            if (EPI == 0) {
                if (is_qkv) {
                    float b0 = bsel[head * 128 + cloc], b1 = bsel[head * 128 + cloc + 1];
                    float v00 = acc[i][j][0] + b0, v01 = acc[i][j][1] + b1;
                    float v10 = acc[i][j][2] + b0, v11 = acc[i][j][3] + b1;
                    size_t base = (((size_t)sec * NH_ + head) * S_ + r0) * DH_ + cloc;
                    *(float2*)(C + base) = make_float2(v00, v01);
                    *(float2*)(C + base + 8 * DH_) = make_float2(v10, v11);
                } else {
                    int col = (blockIdx.y - 72) * 128 + cloc;
                    float b0 = mlpb[col], b1 = mlpb[col + 1];
                    float v00 = gelu_tanh(acc[i][j][0] + b0), v01 = gelu_tanh(acc[i][j][1] + b1);
                    float v10 = gelu_tanh(acc[i][j][2] + b0), v11 = gelu_tanh(acc[i][j][3] + b1);
                    uint32_t h0, l0, h1, l1;
                    split2(v00, v01, h0, l0);
                    split2(v10, v11, h1, l1);
                    size_t base = (size_t)r0 * FD_ + D_ + col;
                    *(uint32_t*)(fhi + base) = h0;
                    *(uint32_t*)(flo + base) = l0;
                    *(uint32_t*)(fhi + base + (size_t)8 * FD_) = h1;
                    *(uint32_t*)(flo + base + (size_t)8 * FD_) = l1;
                }
            } else {   // EPI == 3: raw split-K partial
                int cg = blockIdx.y * 128 + cloc;
                size_t base = (size_t)r0 * D_ + cg;
                *(float2*)(Cz + base) = make_float2(acc[i][j][0], acc[i][j][1]);
                *(float2*)(Cz + base + 8 * D_) = make_float2(acc[i][j][2], acc[i][j][3]);
            }
        }
    }
}

// ---------------- split-K reduce + bias + gate + residual ----------------
__global__ void __launch_bounds__(256) redout_k(const float* __restrict__ bias,
                                                const float* __restrict__ gate,
                                                const float* __restrict__ resid,
                                                float* __restrict__ out) {
    int i = blockIdx.x * 256 + threadIdx.x;              // float4 index
    if (i >= (int)((size_t)S_ * D_ / 4)) return;
    int col4 = (i % (D_ / 4)) * 4;
    const float4* p0 = (const float4*)g_part + i;
    const float4* p1 = (const float4*)(g_part + (size_t)S_ * D_) + i;
    const float4* p2 = (const float4*)(g_part + (size_t)2 * S_ * D_) + i;
    float4 a = *p0, b = *p1, c = *p2;
    float4 bs = *(const float4*)(bias + col4);
    float4 gt = *(const float4*)(gate + col4);
    float4 rv = ((const float4*)resid)[i];
    float4 o;
    o.x = rv.x + gt.x * (a.x + b.x + c.x + bs.x);
    o.y = rv.y + gt.y * (a.y + b.y + c.y + bs.y);
    o.z = rv.z + gt.z * (a.z + b.z + c.z + bs.z);
    o.w = rv.w + gt.w * (a.w + b.w + c.w + bs.w);
    ((float4*)out)[i] = o;
}

// ---------------- per-head RMSNorm + RoPE + bf16 hi/lo split (q,k,v) ----------------
__global__ void __launch_bounds__(128) rmsrope_k(const float* __restrict__ cosb,
                                                 const float* __restrict__ sinb,
                                                 const float* __restrict__ qrw,
                                                 const float* __restrict__ krw) {
    int s = blockIdx.x, h = blockIdx.y, j = threadIdx.x;
    size_t idx = ((size_t)h * S_ + s) * DH_ + j;
    float qv = g_qkv[idx], kv = g_qkv[NHSD + idx], vv = g_qkv[2 * NHSD + idx];
    float q2 = qv * qv, k2 = kv * kv;
#pragma unroll
    for (int o = 16; o; o >>= 1) {
        q2 += __shfl_xor_sync(0xffffffffu, q2, o);
        k2 += __shfl_xor_sync(0xffffffffu, k2, o);
    }
    __shared__ float sq[4], sk[4];
    int w = j >> 5;
    if ((j & 31) == 0) { sq[w] = q2; sk[w] = k2; }
    __syncthreads();
    float qsum = sq[0] + sq[1] + sq[2] + sq[3];
    float ksum = sk[0] + sk[1] + sk[2] + sk[3];
    float qr = rsqrtf(qsum * (1.f / DH_) + EPSV);
    float kr = rsqrtf(ksum * (1.f / DH_) + EPSV);
    qv *= qr * qrw[j];
    kv *= kr * krw[j];
    float qp = __shfl_xor_sync(0xffffffffu, qv, 1);
    float kp = __shfl_xor_sync(0xffffffffu, kv, 1);
    float qrot = (j & 1) ? qp : -qp;
    float krot = (j & 1) ? kp : -kp;
    float c = cosb[s * DH_ + j], sn = sinb[s * DH_ + j];
    float qf = qv * c + qrot * sn;
    float kf = kv * c + krot * sn;
    __nv_bfloat16 qh = __float2bfloat16(qf);
    __nv_bfloat16 kh = __float2bfloat16(kf);
    __nv_bfloat16 vh = __float2bfloat16(vv);
    g_qsh[idx] = qh; g_qsl[idx] = __float2bfloat16(qf - __bfloat162float(qh));
    g_ksh[idx] = kh; g_ksl[idx] = __float2bfloat16(kf - __bfloat162float(kh));
    g_vsh[idx] = vh; g_vsl[idx] = __float2bfloat16(vv - __bfloat162float(vh));
}

// ---------------- tensor-core flash attention ----------------
// 8 warps, q tile 128 (16 rows/warp), kv tile 64, split-bf16 3-pass QK^T and P.V
#define ASTR   136
#define QHALF  (128 * ASTR)
#define KVHALF (64 * ASTR)
#define STGHALF (4 * KVHALF)
#define ATT2_SMEM ((2 * QHALF + 2 * STGHALF) * 2)   // 208896 bytes

__global__ void __launch_bounds__(256, 1) attn2_k(__nv_bfloat16* __restrict__ fh,
                                                  __nv_bfloat16* __restrict__ fl) {
    extern __shared__ __align__(16) char smraw[];
    const uint32_t sb = smem_u32(smraw);
    const int tid = threadIdx.x, lane = tid & 31, wid = tid >> 5;
    const int h = blockIdx.y, qt = blockIdx.x;
    const __nv_bfloat16* Qgh = g_qsh + ((size_t)h * S_ + (size_t)qt * 128) * DH_;
    const __nv_bfloat16* Qgl = g_qsl + ((size_t)h * S_ + (size_t)qt * 128) * DH_;
    const __nv_bfloat16* Kgh = g_ksh + (size_t)h * S_ * DH_;
    const __nv_bfloat16* Kgl = g_ksl + (size_t)h * S_ * DH_;
    const __nv_bfloat16* Vgh = g_vsh + (size_t)h * S_ * DH_;
    const __nv_bfloat16* Vgl = g_vsl + (size_t)h * S_ * DH_;

    const uint32_t uQh = sb, uQl = sb + QHALF * 2;
    const uint32_t uStage = sb + 2 * QHALF * 2;

    auto issueKV = [&](int st, int kt) {
        uint32_t base = uStage + (uint32_t)st * STGHALF * 2;
#pragma unroll
        for (int it = 0; it < 16; it++) {
            int cidx = tid + it * 256;
            int mat = cidx >> 10, rem = cidx & 1023;
            int row = rem >> 4, c8 = rem & 15;
            const __nv_bfloat16* src;
            if (mat == 0) src = Kgh; else if (mat == 1) src = Kgl;
            else if (mat == 2) src = Vgh; else src = Vgl;
            CP_ASYNC16(base + (uint32_t)(mat * KVHALF + row * ASTR + c8 * 8) * 2,
                       src + ((size_t)(kt * 64 + row)) * DH_ + c8 * 8);
        }
    };
#pragma unroll
    for (int it = 0; it < 8; it++) {
        int cidx = tid + it * 256;
        int row = cidx >> 4, c8 = cidx & 15;
        CP_ASYNC16(uQh + (uint32_t)(row * ASTR + c8 * 8) * 2, Qgh + (size_t)row * DH_ + c8 * 8);
        CP_ASYNC16(uQl + (uint32_t)(row * ASTR + c8 * 8) * 2, Qgl + (size_t)row * DH_ + c8 * 8);
    }
    issueKV(0, 0); CP_COMMIT();
    issueKV(1, 1); CP_COMMIT();

    float o[16][4];
#pragma unroll
    for (int n = 0; n < 16; n++)
#pragma unroll
        for (int u = 0; u < 4; u++) o[n][u] = 0.f;
    float m0 = -3.0e38f, m1 = -3.0e38f, l0 = 0.f, l1 = 0.f;
    const int r0 = wid * 16;
    const float scale = 0.08838834764831845f;

    for (int kt = 0; kt < S_ / 64; kt++) {
        CP_WAIT1();
        __syncthreads();
        const uint32_t base = uStage + (uint32_t)(kt & 1) * STGHALF * 2;

        float sc[8][4];
#pragma unroll
        for (int n = 0; n < 8; n++)
#pragma unroll
            for (int u = 0; u < 4; u++) sc[n][u] = 0.f;
#pragma unroll
        for (int kc = 0; kc < 8; kc++) {
            uint32_t qh4[4], ql4[4];
            uint32_t qoff = (uint32_t)((r0 + (lane & 15)) * ASTR + kc * 16 + (lane >> 4) * 8) * 2;
            LDSM4(qh4, uQh + qoff);
            LDSM4(ql4, uQl + qoff);
            uint32_t kh4[4][4], kl4[4][4];
#pragma unroll
            for (int jp = 0; jp < 4; jp++) {
                uint32_t koff = base + (uint32_t)(((2 * jp + (lane >> 4)) * 8 + (lane & 7)) * ASTR +
                                                  kc * 16 + ((lane >> 3) & 1) * 8) * 2;
                LDSM4(kh4[jp], koff);
                LDSM4(kl4[jp], koff + KVHALF * 2);
            }
#pragma unroll
            for (int jp = 0; jp < 4; jp++) {
                MMA_BF16(sc[2 * jp],     qh4, kh4[jp]);
                MMA_BF16(sc[2 * jp + 1], qh4, kh4[jp] + 2);
            }
#pragma unroll
            for (int jp = 0; jp < 4; jp++) {
                MMA_BF16(sc[2 * jp],     qh4, kl4[jp]);
                MMA_BF16(sc[2 * jp + 1], qh4, kl4[jp] + 2);
            }
#pragma unroll
            for (int jp = 0; jp < 4; jp++) {
                MMA_BF16(sc[2 * jp],     ql4, kh4[jp]);
                MMA_BF16(sc[2 * jp + 1], ql4, kh4[jp] + 2);
            }
        }
        float mx0 = -3.0e38f, mx1 = -3.0e38f;
#pragma unroll
        for (int n = 0; n < 8; n++) {
            sc[n][0] *= scale; sc[n][1] *= scale; sc[n][2] *= scale; sc[n][3] *= scale;
            mx0 = fmaxf(mx0, fmaxf(sc[n][0], sc[n][1]));
            mx1 = fmaxf(mx1, fmaxf(sc[n][2], sc[n][3]));
        }
        mx0 = fmaxf(mx0, __shfl_xor_sync(0xffffffffu, mx0, 1));
        mx0 = fmaxf(mx0, __shfl_xor_sync(0xffffffffu, mx0, 2));
        mx1 = fmaxf(mx1, __shfl_xor_sync(0xffffffffu, mx1, 1));
        mx1 = fmaxf(mx1, __shfl_xor_sync(0xffffffffu, mx1, 2));
        float m0n = fmaxf(m0, mx0), m1n = fmaxf(m1, mx1);
        float c0 = __expf(m0 - m0n), c1 = __expf(m1 - m1n);
        m0 = m0n; m1 = m1n;
        uint32_t pah[4][4], pal[4][4];
        float s0 = 0.f, s1 = 0.f;
#pragma unroll
        for (int t = 0; t < 4; t++) {
            float p00 = __expf(sc[2 * t][0] - m0n),     p01 = __expf(sc[2 * t][1] - m0n);
            float p02 = __expf(sc[2 * t][2] - m1n),     p03 = __expf(sc[2 * t][3] - m1n);
            float p10 = __expf(sc[2 * t + 1][0] - m0n), p11 = __expf(sc[2 * t + 1][1] - m0n);
            float p12 = __expf(sc[2 * t + 1][2] - m1n), p13 = __expf(sc[2 * t + 1][3] - m1n);
            s0 += p00 + p01 + p10 + p11;
            s1 += p02 + p03 + p12 + p13;
            split2(p00, p01, pah[t][0], pal[t][0]);
            split2(p02, p03, pah[t][1], pal[t][1]);
            split2(p10, p11, pah[t][2], pal[t][2]);
            split2(p12, p13, pah[t][3], pal[t][3]);
        }
        s0 += __shfl_xor_sync(0xffffffffu, s0, 1);
        s0 += __shfl_xor_sync(0xffffffffu, s0, 2);
        s1 += __shfl_xor_sync(0xffffffffu, s1, 1);
        s1 += __shfl_xor_sync(0xffffffffu, s1, 2);
        l0 = l0 * c0 + s0;
        l1 = l1 * c1 + s1;
#pragma unroll
        for (int n = 0; n < 16; n++) {
            o[n][0] *= c0; o[n][1] *= c0; o[n][2] *= c1; o[n][3] *= c1;
        }
#pragma unroll
        for (int t = 0; t < 4; t++) {
#pragma unroll
            for (int dp = 0; dp < 8; dp += 2) {
                uint32_t vh4[2][4], vl4[2][4];
#pragma unroll
                for (int u = 0; u < 2; u++) {
                    uint32_t voff = base + (uint32_t)(2 * KVHALF +
                                    (t * 16 + (lane & 7) + ((lane & 8) ? 8 : 0)) * ASTR +
                                    (dp + u) * 16 + ((lane & 16) ? 8 : 0)) * 2;
                    LDSM4T(vh4[u], voff);
                    LDSM4T(vl4[u], voff + KVHALF * 2);
                }
#pragma unroll
                for (int u = 0; u < 2; u++) {
                    MMA_BF16(o[2 * (dp + u)],     pah[t], vh4[u]);
                    MMA_BF16(o[2 * (dp + u) + 1], pah[t], vh4[u] + 2);
                }
#pragma unroll
                for (int u = 0; u < 2; u++) {
                    MMA_BF16(o[2 * (dp + u)],     pah[t], vl4[u]);
                    MMA_BF16(o[2 * (dp + u) + 1], pah[t], vl4[u] + 2);
                }
#pragma unroll
                for (int u = 0; u < 2; u++) {
                    MMA_BF16(o[2 * (dp + u)],     pal[t], vh4[u]);
                    MMA_BF16(o[2 * (dp + u) + 1], pal[t], vh4[u] + 2);
                }
            }
        }
        __syncthreads();
        if (kt + 2 < S_ / 64) issueKV(kt & 1, kt + 2);
        CP_COMMIT();
    }
    float inv0 = 1.f / l0, inv1 = 1.f / l1;
    int ra = qt * 128 + r0 + (lane >> 2);
    int rb = ra + 8;
    int cb = h * DH_ + (lane & 3) * 2;
#pragma unroll
    for (int dn = 0; dn < 16; dn++) {
        uint32_t hh, ll;
        split2(o[dn][0] * inv0, o[dn][1] * inv0, hh, ll);
        *(uint32_t*)(fh + (size_t)ra * FD_ + cb + dn * 8) = hh;
        *(uint32_t*)(fl + (size_t)ra * FD_ + cb + dn * 8) = ll;
        split2(o[dn][2] * inv1, o[dn][3] * inv1, hh, ll);
        *(uint32_t*)(fh + (size_t)rb * FD_ + cb + dn * 8) = hh;
        *(uint32_t*)(fl + (size_t)rb * FD_ + cb + dn * 8) = ll;
    }
}

// ---------------- launch ----------------
extern "C" void kernel_launch(void* const* d_in, const int* in_sizes, int n_in,
                              void* d_out, int out_size) {
    (void)in_sizes; (void)n_in; (void)out_size;
    const float* hidden = (const float*)d_in[0];
    const float* temb   = (const float*)d_in[1];
    const float* cosb   = (const float*)d_in[2];
    const float* sinb   = (const float*)d_in[3];
    const float* norm_w = (const float*)d_in[4];
    const float* norm_b = (const float*)d_in[5];
    const float* qw = (const float*)d_in[6];
    const float* qb = (const float*)d_in[7];
    const float* kw = (const float*)d_in[8];
    const float* kb = (const float*)d_in[9];
    const float* vw = (const float*)d_in[10];
    const float* vb = (const float*)d_in[11];
    const float* qrw = (const float*)d_in[12];
    const float* krw = (const float*)d_in[13];
    const float* mlp_w = (const float*)d_in[14];
    const float* mlp_b = (const float*)d_in[15];
    const float* out_w = (const float*)d_in[16];
    const float* out_b = (const float*)d_in[17];
    float* out = (float*)d_out;

    void *p_qkv, *p_fh, *p_fl, *p_emb, *p_wh, *p_wl, *p_nxh, *p_nxl, *p_part;
    cudaGetSymbolAddress(&p_nxh, g_nx_hi);
    cudaGetSymbolAddress(&p_nxl, g_nx_lo);
    cudaGetSymbolAddress(&p_qkv, g_qkv);
    cudaGetSymbolAddress(&p_fh, g_f_hi);
    cudaGetSymbolAddress(&p_fl, g_f_lo);
    cudaGetSymbolAddress(&p_emb, g_emb);
    cudaGetSymbolAddress(&p_wh, g_w_hi);
    cudaGetSymbolAddress(&p_wl, g_w_lo);
    cudaGetSymbolAddress(&p_part, g_part);
    __nv_bfloat16* wh = (__nv_bfloat16*)p_wh;
    __nv_bfloat16* wl = (__nv_bfloat16*)p_wl;
    const __nv_bfloat16* nxh = (const __nv_bfloat16*)p_nxh;
    const __nv_bfloat16* nxl = (const __nv_bfloat16*)p_nxl;
    const __nv_bfloat16* fh = (const __nv_bfloat16*)p_fh;
    const __nv_bfloat16* fl = (const __nv_bfloat16*)p_fl;

    cudaFuncSetAttribute(mgemm_k<0>, cudaFuncAttributeMaxDynamicSharedMemorySize, GSMEM);
    cudaFuncSetAttribute(mgemm_k<3>, cudaFuncAttributeMaxDynamicSharedMemorySize, GSMEM);
    cudaFuncSetAttribute(attn2_k, cudaFuncAttributeMaxDynamicSharedMemorySize, ATT2_SMEM);

    dim3 gfused(S_ / 128, (9216 + M_) / 128);   // 16 x 168, fused q/k/v + mlp
    dim3 gout(S_ / 128, D_ / 128, 3);           // 16 x 24 x 3 split-K

    convall_k<<<dim3((WSEG / 4 + 1023) / 1024, 12), 256>>>(qw, kw, vw, mlp_w, out_w,       // 0
                                                           wh, wl);
    emb_k<<<3 * D_, 128>>>(temb, norm_w, norm_b);                                          // 1
    ln_k<<<S_, 256>>>(hidden);                                                             // 2
    mgemm_k<0><<<gfused, 128, GSMEM>>>(nxh, nxl, wh, wl, D_, D_,                           // 3
                                       (float*)p_qkv, qb, kb, vb, mlp_b,
                                       (__nv_bfloat16*)p_fh, (__nv_bfloat16*)p_fl);
    rmsrope_k<<<dim3(S_, NH_), 128>>>(cosb, sinb, qrw, krw);                               // 4
    attn2_k<<<dim3(S_ / 128, NH_), 256, ATT2_SMEM>>>((__nv_bfloat16*)p_fh,                 // 5
                                                     (__nv_bfloat16*)p_fl);
    mgemm_k<3><<<gout, 128, GSMEM>>>(fh, fl, wh + WOFF_OUT, wl + WOFF_OUT, FD_, KSPL,      // 6
                                     (float*)p_part, nullptr, nullptr, nullptr, nullptr,
                                     nullptr, nullptr);
    redout_k<<<((S_ * D_ / 4) + 255) / 256, 256>>>(out_b, (const float*)p_emb + 2 * D_,    // 7
                                                   hidden, out);
}